// round 3
// baseline (speedup 1.0000x reference)
#include <cuda_runtime.h>
#include <math.h>

#define BB   8
#define NN   2048
#define DIN  256
#define DV   256
#define HH   8
#define HDD  32
#define DFF  512
#define MROWS (BB*NN)   // 16384

// ---------------- scratch (static device memory; no allocations) ----------------
__device__ float g_xn[MROWS*DIN];
__device__ float g_Q [MROWS*DV];
__device__ float g_K [MROWS*DV];   // [B,H,N,HD]
__device__ float g_V [MROWS*DV];   // [B,H,N,HD]
__device__ float g_O [MROWS*DV];
__device__ float g_On[MROWS*DV];
__device__ float g_H1[MROWS*DFF];

// ---------------- layernorm over D=256, one block per row ----------------
__global__ __launch_bounds__(256)
void ln_kernel(const float* __restrict__ src, float* __restrict__ dst,
               const float* __restrict__ gamma, const float* __restrict__ beta)
{
    int row = blockIdx.x;
    int tid = threadIdx.x;
    float v = src[row*256 + tid];
    float s = v, s2 = v*v;
    #pragma unroll
    for (int o = 16; o; o >>= 1) {
        s  += __shfl_xor_sync(0xffffffffu, s,  o);
        s2 += __shfl_xor_sync(0xffffffffu, s2, o);
    }
    __shared__ float ws[8], ws2[8];
    int w = tid >> 5, ln = tid & 31;
    if (ln == 0) { ws[w] = s; ws2[w] = s2; }
    __syncthreads();
    if (w == 0) {
        float a  = (ln < 8) ? ws[ln]  : 0.f;
        float b  = (ln < 8) ? ws2[ln] : 0.f;
        #pragma unroll
        for (int o = 4; o; o >>= 1) {
            a += __shfl_xor_sync(0xffffffffu, a, o);
            b += __shfl_xor_sync(0xffffffffu, b, o);
        }
        if (ln == 0) { ws[0] = a; ws2[0] = b; }
    }
    __syncthreads();
    float mu  = ws[0]  * (1.f/256.f);
    float var = ws2[0] * (1.f/256.f) - mu*mu;
    float inv = rsqrtf(var + 1e-5f);
    dst[row*256 + tid] = (v - mu) * inv * gamma[tid] + beta[tid];
}

// ---------------- tiled SGEMM: C[M x NDIM] = A[M x KDIM] @ W[KDIM x NDIM] ----------------
// BM=BN=64, BK=16, 256 threads, 4x4 microtile per thread.
// MODE 0: out = acc + bias                        (row-major [M,NDIM])
// MODE 1: scatter to [B,H,N,HD] with bias         (for K, V)
// MODE 2: out = gelu(acc + bias)                  (exact gelu, erf)
// MODE 3: out = resid + acc + bias                (final output)
template<int KDIM, int NDIM, int MODE>
__global__ __launch_bounds__(256)
void gemm_kernel(const float* __restrict__ A, const float* __restrict__ W,
                 const float* __restrict__ bias, float* __restrict__ out,
                 const float* __restrict__ resid)
{
    __shared__ float As[64][17];
    __shared__ float Bs[16][64];
    const int tid = threadIdx.x;
    const int tx = tid & 15, ty = tid >> 4;
    const int rowBase = blockIdx.y * 64;
    const int colBase = blockIdx.x * 64;

    float acc[4][4];
    #pragma unroll
    for (int i = 0; i < 4; i++)
        #pragma unroll
        for (int j = 0; j < 4; j++) acc[i][j] = 0.f;

    const int ar = tid >> 2, ac4 = tid & 3;   // A tile: 64 rows x 4 float4
    const int br = tid >> 4, bc4 = tid & 15;  // B tile: 16 rows x 16 float4

    #pragma unroll 1
    for (int kt = 0; kt < KDIM/16; kt++) {
        float4 a4 = *(const float4*)&A[(rowBase + ar)*KDIM + kt*16 + ac4*4];
        As[ar][ac4*4+0] = a4.x; As[ar][ac4*4+1] = a4.y;
        As[ar][ac4*4+2] = a4.z; As[ar][ac4*4+3] = a4.w;
        *(float4*)&Bs[br][bc4*4] =
            *(const float4*)&W[(kt*16 + br)*NDIM + colBase + bc4*4];
        __syncthreads();
        #pragma unroll
        for (int kk = 0; kk < 16; kk++) {
            float4 b4 = *(const float4*)&Bs[kk][tx*4];
            float av[4];
            #pragma unroll
            for (int i = 0; i < 4; i++) av[i] = As[ty*4+i][kk];
            #pragma unroll
            for (int i = 0; i < 4; i++) {
                acc[i][0] += av[i]*b4.x;
                acc[i][1] += av[i]*b4.y;
                acc[i][2] += av[i]*b4.z;
                acc[i][3] += av[i]*b4.w;
            }
        }
        __syncthreads();
    }

    #pragma unroll
    for (int i = 0; i < 4; i++) {
        int r  = rowBase + ty*4 + i;
        int c0 = colBase + tx*4;
        if (MODE == 0) {
            float4 o;
            o.x = acc[i][0] + bias[c0+0];
            o.y = acc[i][1] + bias[c0+1];
            o.z = acc[i][2] + bias[c0+2];
            o.w = acc[i][3] + bias[c0+3];
            *(float4*)&out[r*NDIM + c0] = o;
        } else if (MODE == 1) {
            int b = r >> 11, n = r & (NN-1);
            #pragma unroll
            for (int j = 0; j < 4; j++) {
                int c = c0 + j;
                int h = c >> 5, d = c & 31;
                out[((b*HH + h)*NN + n)*HDD + d] = acc[i][j] + bias[c];
            }
        } else if (MODE == 2) {
            float4 o;
            #pragma unroll
            for (int j = 0; j < 4; j++) {
                float v = acc[i][j] + bias[c0+j];
                float g = 0.5f * v * (1.f + erff(v * 0.70710678118654752f));
                ((float*)&o)[j] = g;
            }
            *(float4*)&out[r*NDIM + c0] = o;
        } else {
            float4 rr = *(const float4*)&resid[r*256 + c0];
            float4 o;
            o.x = rr.x + acc[i][0] + bias[c0+0];
            o.y = rr.y + acc[i][1] + bias[c0+1];
            o.z = rr.z + acc[i][2] + bias[c0+2];
            o.w = rr.w + acc[i][3] + bias[c0+3];
            *(float4*)&out[r*256 + c0] = o;
        }
    }
}

// ---------------- fused flash attention + per-head Q residual ----------------
// grid: (N/128, B*H). block: 256 threads.
// Each block: one (b,h), 128 query rows. Online softmax over 64 k-tiles of 32.
// Thread (ry=tid/8, cx=tid%8): S rows ry*4..+3, S cols cx*4..+3 (tile width 32);
// AV acc rows ry*4..+3, output cols cx*4..+3.
__global__ __launch_bounds__(256)
void attn_kernel(const float* __restrict__ Q, const float* __restrict__ K,
                 const float* __restrict__ V, float* __restrict__ O)
{
    __shared__ float Qs[128][33];
    __shared__ float Ks[32][33];
    __shared__ float Vs[32][32];
    __shared__ float Ps[128][33];

    const int bh = blockIdx.y;           // 0..63
    const int b  = bh >> 3, h = bh & 7;
    const int qbase = blockIdx.x * 128;
    const int tid = threadIdx.x;
    const int ry = tid >> 3;             // 0..31
    const int cx = tid & 7;              // 0..7

    // load Q tile [128 x 32]
    #pragma unroll
    for (int it = 0; it < 4; it++) {
        int idx = tid + it*256;
        int r = idx >> 3, c4 = idx & 7;
        float4 q4 = *(const float4*)&Q[(b*NN + qbase + r)*DV + h*HDD + c4*4];
        Qs[r][c4*4+0] = q4.x; Qs[r][c4*4+1] = q4.y;
        Qs[r][c4*4+2] = q4.z; Qs[r][c4*4+3] = q4.w;
    }

    float m[4], l[4], acc[4][4];
    #pragma unroll
    for (int i = 0; i < 4; i++) {
        m[i] = -INFINITY; l[i] = 0.f;
        #pragma unroll
        for (int j = 0; j < 4; j++) acc[i][j] = 0.f;
    }

    const float* Kb = K + bh*NN*HDD;
    const float* Vb = V + bh*NN*HDD;

    #pragma unroll 1
    for (int kt = 0; kt < NN/32; kt++) {
        __syncthreads();   // previous AV done before overwriting Ks/Vs
        {
            int r = tid >> 3, c4 = tid & 7;   // 32 rows x 8 float4
            float4 k4 = *(const float4*)&Kb[(kt*32 + r)*HDD + c4*4];
            Ks[r][c4*4+0] = k4.x; Ks[r][c4*4+1] = k4.y;
            Ks[r][c4*4+2] = k4.z; Ks[r][c4*4+3] = k4.w;
            float4 v4 = *(const float4*)&Vb[(kt*32 + r)*HDD + c4*4];
            *(float4*)&Vs[r][c4*4] = v4;
        }
        __syncthreads();

        // S = Q K^T (tile 128x32), scale 1/sqrt(256)
        float s[4][4];
        #pragma unroll
        for (int i = 0; i < 4; i++)
            #pragma unroll
            for (int j = 0; j < 4; j++) s[i][j] = 0.f;
        #pragma unroll
        for (int d = 0; d < 32; d++) {
            float qa[4], kb[4];
            #pragma unroll
            for (int i = 0; i < 4; i++) qa[i] = Qs[ry*4+i][d];
            #pragma unroll
            for (int j = 0; j < 4; j++) kb[j] = Ks[cx*4+j][d];
            #pragma unroll
            for (int i = 0; i < 4; i++)
                #pragma unroll
                for (int j = 0; j < 4; j++) s[i][j] += qa[i]*kb[j];
        }

        // online softmax per row (8 lanes per row share via shfl)
        #pragma unroll
        for (int i = 0; i < 4; i++) {
            #pragma unroll
            for (int j = 0; j < 4; j++) s[i][j] *= 0.0625f;
            float rm = fmaxf(fmaxf(s[i][0], s[i][1]), fmaxf(s[i][2], s[i][3]));
            #pragma unroll
            for (int o = 1; o < 8; o <<= 1)
                rm = fmaxf(rm, __shfl_xor_sync(0xffffffffu, rm, o));
            float nm = fmaxf(m[i], rm);
            float sc = __expf(m[i] - nm);
            float rs = 0.f;
            #pragma unroll
            for (int j = 0; j < 4; j++) {
                s[i][j] = __expf(s[i][j] - nm);
                rs += s[i][j];
            }
            #pragma unroll
            for (int o = 1; o < 8; o <<= 1)
                rs += __shfl_xor_sync(0xffffffffu, rs, o);
            l[i] = l[i]*sc + rs;
            m[i] = nm;
            #pragma unroll
            for (int j = 0; j < 4; j++) acc[i][j] *= sc;
            #pragma unroll
            for (int j = 0; j < 4; j++) Ps[ry*4+i][cx*4+j] = s[i][j];
        }
        __syncthreads();

        // acc += P @ V  (thread owns rows ry*4..+3, cols cx*4..+3)
        #pragma unroll
        for (int k = 0; k < 32; k++) {
            float4 v4 = *(const float4*)&Vs[k][cx*4];
            #pragma unroll
            for (int i = 0; i < 4; i++) {
                float p = Ps[ry*4+i][k];
                acc[i][0] += p*v4.x;
                acc[i][1] += p*v4.y;
                acc[i][2] += p*v4.z;
                acc[i][3] += p*v4.w;
            }
        }
    }

    // epilogue: O = Q + softmax(S) V
    #pragma unroll
    for (int i = 0; i < 4; i++) {
        int r = ry*4 + i;
        float inv = 1.f / l[i];
        float4 o;
        o.x = Qs[r][cx*4+0] + acc[i][0]*inv;
        o.y = Qs[r][cx*4+1] + acc[i][1]*inv;
        o.z = Qs[r][cx*4+2] + acc[i][2]*inv;
        o.w = Qs[r][cx*4+3] + acc[i][3]*inv;
        *(float4*)&O[(b*NN + qbase + r)*DV + h*HDD + cx*4] = o;
    }
}

// ---------------- launch ----------------
extern "C" void kernel_launch(void* const* d_in, const int* /*in_sizes*/, int /*n_in*/,
                              void* d_out, int /*out_size*/)
{
    const float* x     = (const float*)d_in[0];
    const float* y     = (const float*)d_in[1];
    const float* Wq    = (const float*)d_in[2];
    const float* bq    = (const float*)d_in[3];
    const float* Wk    = (const float*)d_in[4];
    const float* bk    = (const float*)d_in[5];
    const float* Wv    = (const float*)d_in[6];
    const float* bv    = (const float*)d_in[7];
    const float* W1    = (const float*)d_in[8];
    const float* b1    = (const float*)d_in[9];
    const float* W2    = (const float*)d_in[10];
    const float* b2    = (const float*)d_in[11];
    const float* ln0_g = (const float*)d_in[12];
    const float* ln0_b = (const float*)d_in[13];
    const float* ln1_g = (const float*)d_in[14];
    const float* ln1_b = (const float*)d_in[15];
    float* out = (float*)d_out;

    float *xn, *Q, *K, *V, *O, *On, *H1;
    cudaGetSymbolAddress((void**)&xn, g_xn);
    cudaGetSymbolAddress((void**)&Q,  g_Q);
    cudaGetSymbolAddress((void**)&K,  g_K);
    cudaGetSymbolAddress((void**)&V,  g_V);
    cudaGetSymbolAddress((void**)&O,  g_O);
    cudaGetSymbolAddress((void**)&On, g_On);
    cudaGetSymbolAddress((void**)&H1, g_H1);

    ln_kernel<<<MROWS, 256>>>(x, xn, ln0_g, ln0_b);
    gemm_kernel<256,256,0><<<dim3(4,  MROWS/64), 256>>>(xn, Wq, bq, Q,  nullptr);
    gemm_kernel<256,256,1><<<dim3(4,  MROWS/64), 256>>>(y,  Wk, bk, K,  nullptr);
    gemm_kernel<256,256,1><<<dim3(4,  MROWS/64), 256>>>(y,  Wv, bv, V,  nullptr);
    attn_kernel<<<dim3(NN/128, BB*HH), 256>>>(Q, K, V, O);
    ln_kernel<<<MROWS, 256>>>(O, On, ln1_g, ln1_b);
    gemm_kernel<256,512,2><<<dim3(8,  MROWS/64), 256>>>(On, W1, b1, H1, nullptr);
    gemm_kernel<512,256,3><<<dim3(4,  MROWS/64), 256>>>(H1, W2, b2, out, O);
}

// round 4
// speedup vs baseline: 3.1148x; 3.1148x over previous
#include <cuda_runtime.h>
#include <math.h>

#define BB 8
#define NN 2048
#define DV 256
#define HH 8
#define DFF 512
#define MROWS (BB*NN)

__device__ float g_xn[MROWS*DV];
__device__ float g_Q [MROWS*DV];   // [B,H,N,32] fp32 exact
__device__ float g_K [MROWS*DV];   // [B,H,N,32] token+d phi-permuted, tf32-rounded
__device__ float g_V [MROWS*DV];   // [B,H,32,N] token phi-permuted, tf32-rounded
__device__ float g_O [MROWS*DV];
__device__ float g_On[MROWS*DV];
__device__ float g_H1[MROWS*DFF];

__device__ __forceinline__ unsigned f2tf(float x){
    unsigned r; asm("cvt.rna.tf32.f32 %0, %1;" : "=r"(r) : "f"(x)); return r;
}
__device__ __forceinline__ float f2tff(float x){ return __uint_as_float(f2tf(x)); }
__device__ __forceinline__ void mma8(float* c, unsigned a0,unsigned a1,unsigned a2,unsigned a3,
                                     unsigned b0,unsigned b1){
    asm volatile("mma.sync.aligned.m16n8k8.row.col.f32.tf32.tf32.f32 "
      "{%0,%1,%2,%3}, {%4,%5,%6,%7}, {%8,%9}, {%0,%1,%2,%3};"
      : "+f"(c[0]),"+f"(c[1]),"+f"(c[2]),"+f"(c[3])
      : "r"(a0),"r"(a1),"r"(a2),"r"(a3),"r"(b0),"r"(b1));
}
__device__ __forceinline__ int phi8(int v){ return ((v&3)<<1)|((v>>2)&1); }
__device__ __forceinline__ void cpa16(void* smem, const void* gmem){
    unsigned s = (unsigned)__cvta_generic_to_shared(smem);
    asm volatile("cp.async.cg.shared.global [%0], [%1], 16;" :: "r"(s), "l"(gmem));
}

// ---------------- layernorm (D=256), one block per row ----------------
__global__ __launch_bounds__(256)
void ln_kernel(const float* __restrict__ src, float* __restrict__ dst,
               const float* __restrict__ gamma, const float* __restrict__ beta)
{
    int row = blockIdx.x, tid = threadIdx.x;
    float v = src[row*256 + tid];
    float s = v, s2 = v*v;
    #pragma unroll
    for (int o = 16; o; o >>= 1) {
        s  += __shfl_xor_sync(0xffffffffu, s,  o);
        s2 += __shfl_xor_sync(0xffffffffu, s2, o);
    }
    __shared__ float ws[8], ws2[8];
    int w = tid >> 5, ln = tid & 31;
    if (ln == 0) { ws[w] = s; ws2[w] = s2; }
    __syncthreads();
    if (w == 0) {
        float a  = (ln < 8) ? ws[ln]  : 0.f;
        float b  = (ln < 8) ? ws2[ln] : 0.f;
        #pragma unroll
        for (int o = 4; o; o >>= 1) {
            a += __shfl_xor_sync(0xffffffffu, a, o);
            b += __shfl_xor_sync(0xffffffffu, b, o);
        }
        if (ln == 0) { ws[0] = a; ws2[0] = b; }
    }
    __syncthreads();
    float mu  = ws[0]*(1.f/256.f);
    float var = ws2[0]*(1.f/256.f) - mu*mu;
    float inv = rsqrtf(var + 1e-5f);
    dst[row*256 + tid] = (v - mu)*inv*gamma[tid] + beta[tid];
}

// ---------------- tensor-core GEMM  C[M x NDIM] = A[M x KDIM] @ W[KDIM x NDIM] ------------
// BM=256 (8 warps x m32), BN=64, BK=16, mma m16n8k8 tf32.
// MODE 0: Q -> [B,H,N,32] fp32 exact
// MODE 1: K -> [B,H,N,32] token&d phi-permuted, rounded
// MODE 2: V -> [B,H,32,N] token phi-permuted, rounded
// MODE 3: gelu(acc+bias) row-major
// MODE 4: resid + acc + bias row-major
template<int KDIM,int NDIM,int MODE>
__global__ __launch_bounds__(256)
void gemm_tc(const float* __restrict__ A, const float* __restrict__ W,
             const float* __restrict__ bias, float* __restrict__ out,
             const float* __restrict__ resid)
{
    __shared__ unsigned As[256*24];   // [m][k-phys] stride 24, k phi-permuted in 8-groups
    __shared__ unsigned Bs[16*72];    // [k][n] stride 72
    const int tid  = threadIdx.x;
    const int warp = tid>>5, lane = tid&31, g = lane>>2, c = lane&3;
    const int rowBase = blockIdx.y*256;
    const int colBase = blockIdx.x*64;

    float acc[2][8][4];
    #pragma unroll
    for(int mt=0;mt<2;mt++)
        #pragma unroll
        for(int nt=0;nt<8;nt++)
            #pragma unroll
            for(int j=0;j<4;j++) acc[mt][nt][j]=0.f;

    float4 aReg[4]; float4 bReg;
    #pragma unroll
    for(int i=0;i<4;i++){
        int idx = tid + i*256;
        aReg[i] = *(const float4*)&A[(rowBase + (idx>>2))*KDIM + (idx&3)*4];
    }
    bReg = *(const float4*)&W[(tid>>4)*NDIM + colBase + (tid&15)*4];

    const int NK = KDIM/16;
    #pragma unroll 1
    for(int kt=0; kt<NK; kt++){
        __syncthreads();
        #pragma unroll
        for(int i=0;i<4;i++){
            int idx = tid + i*256;
            int m = idx>>2, k4 = idx&3;
            const float* av = (const float*)&aReg[i];
            #pragma unroll
            for(int j=0;j<4;j++){
                int k = k4*4 + j;
                As[m*24 + ((k&8)|phi8(k&7))] = f2tf(av[j]);
            }
        }
        {
            unsigned* bp = &Bs[(tid>>4)*72 + (tid&15)*4];
            bp[0]=f2tf(bReg.x); bp[1]=f2tf(bReg.y); bp[2]=f2tf(bReg.z); bp[3]=f2tf(bReg.w);
        }
        __syncthreads();
        if(kt+1 < NK){
            #pragma unroll
            for(int i=0;i<4;i++){
                int idx = tid + i*256;
                aReg[i] = *(const float4*)&A[(rowBase + (idx>>2))*KDIM + (kt+1)*16 + (idx&3)*4];
            }
            bReg = *(const float4*)&W[((kt+1)*16 + (tid>>4))*NDIM + colBase + (tid&15)*4];
        }
        #pragma unroll
        for(int ks=0;ks<2;ks++){
            unsigned af[2][4];
            #pragma unroll
            for(int mt=0;mt<2;mt++){
                int r = warp*32 + mt*16 + g;
                uint2 lo = *(const uint2*)&As[ r   *24 + ks*8 + 2*c];
                uint2 hi = *(const uint2*)&As[(r+8)*24 + ks*8 + 2*c];
                af[mt][0]=lo.x; af[mt][2]=lo.y; af[mt][1]=hi.x; af[mt][3]=hi.y;
            }
            #pragma unroll
            for(int nt=0;nt<8;nt++){
                unsigned b0 = Bs[(ks*8 + c    )*72 + nt*8 + g];
                unsigned b1 = Bs[(ks*8 + c + 4)*72 + nt*8 + g];
                mma8(acc[0][nt], af[0][0],af[0][1],af[0][2],af[0][3], b0,b1);
                mma8(acc[1][nt], af[1][0],af[1][1],af[1][2],af[1][3], b0,b1);
            }
        }
    }

    #pragma unroll
    for(int mt=0;mt<2;mt++)
    #pragma unroll
    for(int i=0;i<2;i++){
        int r = rowBase + warp*32 + mt*16 + g + i*8;
        #pragma unroll
        for(int nt=0;nt<8;nt++){
            int col0 = colBase + nt*8 + 2*c;
            float v0 = acc[mt][nt][i*2+0] + bias[col0];
            float v1 = acc[mt][nt][i*2+1] + bias[col0+1];
            if(MODE==0){
                int b = r>>11, n = r&2047;
                int h = col0>>5, d = col0&31;
                float2 o; o.x = v0; o.y = v1;
                *(float2*)&out[((b*HH+h)*NN + n)*32 + d] = o;
            } else if(MODE==1){
                int b = r>>11, n = r&2047;
                int np = (n & ~7) | phi8(n&7);
                int h = col0>>5;
                int d0 = col0&31, d1 = d0+1;
                out[((b*HH+h)*NN + np)*32 + ((d0&24)|phi8(d0&7))] = f2tff(v0);
                out[((b*HH+h)*NN + np)*32 + ((d1&24)|phi8(d1&7))] = f2tff(v1);
            } else if(MODE==2){
                int b = r>>11, n = r&2047;
                int np = (n & ~7) | phi8(n&7);
                int h = col0>>5, d = col0&31;
                out[((b*HH+h)*32 + d  )*NN + np] = f2tff(v0);
                out[((b*HH+h)*32 + d+1)*NN + np] = f2tff(v1);
            } else if(MODE==3){
                float g0 = 0.5f*v0*(1.f+erff(v0*0.70710678118654752f));
                float g1 = 0.5f*v1*(1.f+erff(v1*0.70710678118654752f));
                float2 o; o.x=g0; o.y=g1;
                *(float2*)&out[r*NDIM + col0] = o;
            } else {
                float2 rr = *(const float2*)&resid[r*NDIM + col0];
                float2 o; o.x = rr.x+v0; o.y = rr.y+v1;
                *(float2*)&out[r*NDIM + col0] = o;
            }
        }
    }
}

// ---------------- tensor-core flash attention + per-head Q residual ----------------
// grid (N/128, B*H), 8 warps; warp w owns q rows w*16..+15. Key tile 64, cp.async x2 buf.
// S C-frag reused directly as PV A-frag via phi-permuted K/V token layout.
__global__ __launch_bounds__(256)
void attn_tc(const float* __restrict__ Q, const float* __restrict__ K,
             const float* __restrict__ V, float* __restrict__ O)
{
    __shared__ float Ks[2][64*40];  // [key-phys][d-phys] stride 40
    __shared__ float Vs[2][32*72];  // [d][key-phys]      stride 72
    const int tid  = threadIdx.x;
    const int warp = tid>>5, lane = tid&31, g = lane>>2, c = lane&3;
    const int bh = blockIdx.y;
    const int b  = bh>>3, h = bh&7;
    const int qbase = blockIdx.x*128;
    const float* Qg = Q + (bh*NN + qbase)*32;
    const float* Kg = K + (long)bh*NN*32;
    const float* Vg = V + (long)bh*32*NN;

    // Q fragments, scaled by 1/16 (exact pow2) and rna-rounded to tf32
    unsigned qf[4][4];
    #pragma unroll
    for(int ks=0;ks<4;ks++){
        int r0 = warp*16 + g;
        qf[ks][0] = f2tf(Qg[ r0   *32 + ks*8 + c    ] * 0.0625f);
        qf[ks][1] = f2tf(Qg[(r0+8)*32 + ks*8 + c    ] * 0.0625f);
        qf[ks][2] = f2tf(Qg[ r0   *32 + ks*8 + c + 4] * 0.0625f);
        qf[ks][3] = f2tf(Qg[(r0+8)*32 + ks*8 + c + 4] * 0.0625f);
    }

    float oacc[4][4];
    #pragma unroll
    for(int nt=0;nt<4;nt++)
        #pragma unroll
        for(int j=0;j<4;j++) oacc[nt][j]=0.f;
    float l0 = 0.f, l1 = 0.f;

    #pragma unroll
    for(int i=0;i<2;i++){
        int idx = tid + i*256;
        cpa16(&Ks[0][(idx>>3)*40 + (idx&7)*4], Kg + (idx>>3)*32 + (idx&7)*4);
    }
    #pragma unroll
    for(int i=0;i<2;i++){
        int idx = tid + i*256;
        cpa16(&Vs[0][(idx>>4)*72 + (idx&15)*4], Vg + (idx>>4)*NN + (idx&15)*4);
    }
    asm volatile("cp.async.commit_group;");

    #pragma unroll 1
    for(int kt=0; kt<NN/64; kt++){
        int buf = kt&1;
        __syncthreads();                    // all warps done with buf^1
        if(kt+1 < NN/64){
            #pragma unroll
            for(int i=0;i<2;i++){
                int idx = tid + i*256;
                cpa16(&Ks[buf^1][(idx>>3)*40 + (idx&7)*4],
                      Kg + ((kt+1)*64 + (idx>>3))*32 + (idx&7)*4);
            }
            #pragma unroll
            for(int i=0;i<2;i++){
                int idx = tid + i*256;
                cpa16(&Vs[buf^1][(idx>>4)*72 + (idx&15)*4],
                      Vg + (idx>>4)*NN + (kt+1)*64 + (idx&15)*4);
            }
            asm volatile("cp.async.commit_group;");
            asm volatile("cp.async.wait_group 1;");
        } else {
            asm volatile("cp.async.wait_group 0;");
        }
        __syncthreads();                    // tile kt visible

        // S = (Q/16) K^T   (8 key sub-tiles of 8)
        float sv[8][4];
        #pragma unroll
        for(int nt=0;nt<8;nt++)
            #pragma unroll
            for(int j=0;j<4;j++) sv[nt][j]=0.f;
        #pragma unroll
        for(int ks=0;ks<4;ks++){
            #pragma unroll
            for(int nt=0;nt<8;nt++){
                float2 bp = *(const float2*)&Ks[buf][(nt*8+g)*40 + ks*8 + 2*c];
                mma8(sv[nt], qf[ks][0],qf[ks][1],qf[ks][2],qf[ks][3],
                     __float_as_uint(bp.x), __float_as_uint(bp.y));
            }
        }
        // exp (no max; |S/16| small), rounded; l sums the SAME rounded values
        #pragma unroll
        for(int nt=0;nt<8;nt++){
            #pragma unroll
            for(int j=0;j<4;j++){
                float p = f2tff(__expf(sv[nt][j]));
                sv[nt][j] = p;
                if(j<2) l0 += p; else l1 += p;
            }
        }
        // O += P V : S C-frag {c0,c2,c1,c3} is the PV A-frag
        #pragma unroll
        for(int ks=0;ks<8;ks++){
            #pragma unroll
            for(int nt=0;nt<4;nt++){
                float2 bp = *(const float2*)&Vs[buf][(nt*8+g)*72 + ks*8 + 2*c];
                mma8(oacc[nt],
                     __float_as_uint(sv[ks][0]), __float_as_uint(sv[ks][2]),
                     __float_as_uint(sv[ks][1]), __float_as_uint(sv[ks][3]),
                     __float_as_uint(bp.x), __float_as_uint(bp.y));
            }
        }
    }

    // reduce l across the 4 lanes sharing each q-row
    l0 += __shfl_xor_sync(0xffffffffu, l0, 1);
    l0 += __shfl_xor_sync(0xffffffffu, l0, 2);
    l1 += __shfl_xor_sync(0xffffffffu, l1, 1);
    l1 += __shfl_xor_sync(0xffffffffu, l1, 2);
    float inv0 = 1.f/l0, inv1 = 1.f/l1;

    // epilogue: O = Q + (PV)/l  (exact fp32 Q residual)
    #pragma unroll
    for(int i=0;i<2;i++){
        int rloc = warp*16 + g + i*8;
        int row  = qbase + rloc;
        float inv = (i==0) ? inv0 : inv1;
        #pragma unroll
        for(int nt=0;nt<4;nt++){
            int col = nt*8 + 2*c;
            float q0 = Qg[rloc*32 + col];
            float q1 = Qg[rloc*32 + col + 1];
            float2 o;
            o.x = q0 + oacc[nt][i*2+0]*inv;
            o.y = q1 + oacc[nt][i*2+1]*inv;
            *(float2*)&O[((long)b*NN + row)*DV + h*32 + col] = o;
        }
    }
}

// ---------------- launch ----------------
extern "C" void kernel_launch(void* const* d_in, const int* /*in_sizes*/, int /*n_in*/,
                              void* d_out, int /*out_size*/)
{
    const float* x     = (const float*)d_in[0];
    const float* y     = (const float*)d_in[1];
    const float* Wq    = (const float*)d_in[2];
    const float* bq    = (const float*)d_in[3];
    const float* Wk    = (const float*)d_in[4];
    const float* bk    = (const float*)d_in[5];
    const float* Wv    = (const float*)d_in[6];
    const float* bv    = (const float*)d_in[7];
    const float* W1    = (const float*)d_in[8];
    const float* b1    = (const float*)d_in[9];
    const float* W2    = (const float*)d_in[10];
    const float* b2    = (const float*)d_in[11];
    const float* ln0_g = (const float*)d_in[12];
    const float* ln0_b = (const float*)d_in[13];
    const float* ln1_g = (const float*)d_in[14];
    const float* ln1_b = (const float*)d_in[15];
    float* out = (float*)d_out;

    float *xn, *Q, *K, *V, *O, *On, *H1;
    cudaGetSymbolAddress((void**)&xn, g_xn);
    cudaGetSymbolAddress((void**)&Q,  g_Q);
    cudaGetSymbolAddress((void**)&K,  g_K);
    cudaGetSymbolAddress((void**)&V,  g_V);
    cudaGetSymbolAddress((void**)&O,  g_O);
    cudaGetSymbolAddress((void**)&On, g_On);
    cudaGetSymbolAddress((void**)&H1, g_H1);

    ln_kernel<<<MROWS, 256>>>(x, xn, ln0_g, ln0_b);
    gemm_tc<256,256,0><<<dim3(4, 64), 256>>>(xn, Wq, bq, Q,  nullptr);
    gemm_tc<256,256,1><<<dim3(4, 64), 256>>>(y,  Wk, bk, K,  nullptr);
    gemm_tc<256,256,2><<<dim3(4, 64), 256>>>(y,  Wv, bv, V,  nullptr);
    attn_tc<<<dim3(NN/128, BB*HH), 256>>>(Q, K, V, O);
    ln_kernel<<<MROWS, 256>>>(O, On, ln1_g, ln1_b);
    gemm_tc<256,512,3><<<dim3(8, 64), 256>>>(On, W1, b1, H1, nullptr);
    gemm_tc<512,256,4><<<dim3(4, 64), 256>>>(H1, W2, b2, out, O);
}

// round 5
// speedup vs baseline: 3.4114x; 1.0952x over previous
#include <cuda_runtime.h>
#include <math.h>

#define BB 8
#define NN 2048
#define DV 256
#define HH 8
#define DFF 512
#define MROWS (BB*NN)

// ---------------- scratch ----------------
__device__ float g_xn[MROWS*DV];    // ln0 out, rounded+phi-permuted k
__device__ float g_yr[MROWS*DV];    // y rounded+phi-permuted k
__device__ float g_Q [MROWS*DV];    // [B,H,N,32] fp32 exact
__device__ float g_K [MROWS*DV];    // [B,H,N,32] token+d phi-permuted, rounded
__device__ float g_V [MROWS*DV];    // [B,H,32,N] token phi-permuted, rounded
__device__ float g_O [MROWS*DV];    // exact
__device__ float g_On[MROWS*DV];    // ln1 out, rounded+permuted
__device__ float g_H1[MROWS*DFF];   // gelu out, rounded+permuted
__device__ float g_Wq[DV*DV];       // Wt[n][kphys] rounded
__device__ float g_Wk[DV*DV];
__device__ float g_Wv[DV*DV];
__device__ float g_W1[DV*DFF];      // [n=512][k=256]
__device__ float g_W2[DFF*DV];      // [n=256][k=512]

__device__ __forceinline__ unsigned f2tf(float x){
    unsigned r; asm("cvt.rna.tf32.f32 %0, %1;" : "=r"(r) : "f"(x)); return r;
}
__device__ __forceinline__ float f2tff(float x){ return __uint_as_float(f2tf(x)); }
__device__ __forceinline__ void mma8(float* c, unsigned a0,unsigned a1,unsigned a2,unsigned a3,
                                     unsigned b0,unsigned b1){
    asm volatile("mma.sync.aligned.m16n8k8.row.col.f32.tf32.tf32.f32 "
      "{%0,%1,%2,%3}, {%4,%5,%6,%7}, {%8,%9}, {%0,%1,%2,%3};"
      : "+f"(c[0]),"+f"(c[1]),"+f"(c[2]),"+f"(c[3])
      : "r"(a0),"r"(a1),"r"(a2),"r"(a3),"r"(b0),"r"(b1));
}
__device__ __forceinline__ int phi8(int v){ return ((v&3)<<1)|((v>>2)&1); }
__device__ __forceinline__ void cpa16(void* smem, const void* gmem){
    unsigned s = (unsigned)__cvta_generic_to_shared(smem);
    asm volatile("cp.async.cg.shared.global [%0], [%1], 16;" :: "r"(s), "l"(gmem));
}

// ---------------- prep: weights -> Wt[n][kphys], rounded ----------------
__global__ __launch_bounds__(256)
void wprep(const float* __restrict__ W, float* __restrict__ Wt, int KD, int ND){
    int i = blockIdx.x*256 + threadIdx.x;
    if(i >= KD*ND) return;
    int k = i/ND, n = i - k*ND;
    Wt[n*KD + ((k&~7)|phi8(k&7))] = f2tff(W[i]);
}
// ---------------- prep: y -> rounded, phi-permuted low 3 bits ----------------
__global__ __launch_bounds__(256)
void yprep(const float* __restrict__ y, float* __restrict__ yr){
    int i = blockIdx.x*256 + threadIdx.x;
    yr[(i&~7)|phi8(i&7)] = f2tff(y[i]);
}

// ---------------- layernorm (D=256); PERM=1 -> rounded + phi-permuted out ---------------
template<int PERM>
__global__ __launch_bounds__(256)
void ln_kernel(const float* __restrict__ src, float* __restrict__ dst,
               const float* __restrict__ gamma, const float* __restrict__ beta)
{
    int row = blockIdx.x, tid = threadIdx.x;
    float v = src[row*256 + tid];
    float s = v, s2 = v*v;
    #pragma unroll
    for (int o = 16; o; o >>= 1) {
        s  += __shfl_xor_sync(0xffffffffu, s,  o);
        s2 += __shfl_xor_sync(0xffffffffu, s2, o);
    }
    __shared__ float ws[8], ws2[8];
    int w = tid >> 5, ln = tid & 31;
    if (ln == 0) { ws[w] = s; ws2[w] = s2; }
    __syncthreads();
    if (w == 0) {
        float a  = (ln < 8) ? ws[ln]  : 0.f;
        float b  = (ln < 8) ? ws2[ln] : 0.f;
        #pragma unroll
        for (int o = 4; o; o >>= 1) {
            a += __shfl_xor_sync(0xffffffffu, a, o);
            b += __shfl_xor_sync(0xffffffffu, b, o);
        }
        if (ln == 0) { ws[0] = a; ws2[0] = b; }
    }
    __syncthreads();
    float mu  = ws[0]*(1.f/256.f);
    float var = ws2[0]*(1.f/256.f) - mu*mu;
    float inv = rsqrtf(var + 1e-5f);
    float r = (v - mu)*inv*gamma[tid] + beta[tid];
    if(PERM) dst[row*256 + ((tid&~7)|phi8(tid&7))] = f2tff(r);
    else     dst[row*256 + tid] = r;
}

// ---------------- tensor-core GEMM, pre-rounded operands, cp.async pipeline -------------
// A[M][KDIM] phys-permuted rounded; Wt[NDIM][KDIM] phys-permuted rounded.
// BM=256 (8 warps x m32), BN=64, BK=16.
// MODE 0: Q exact  | 1: K attn-layout | 2: V attn-layout | 3: gelu->H1 perm | 4: resid+out
template<int KDIM,int NDIM,int MODE>
__global__ __launch_bounds__(256)
void gemm_tc(const float* __restrict__ A, const float* __restrict__ Wt,
             const float* __restrict__ bias, float* __restrict__ out,
             const float* __restrict__ resid)
{
    __shared__ unsigned As[2][256*24];
    __shared__ unsigned Bs[2][64*24];
    const int tid  = threadIdx.x;
    const int warp = tid>>5, lane = tid&31, g = lane>>2, c = lane&3;
    const int rowBase = blockIdx.y*256;
    const int colBase = blockIdx.x*64;

    float acc[2][8][4];
    #pragma unroll
    for(int mt=0;mt<2;mt++)
        #pragma unroll
        for(int nt=0;nt<8;nt++)
            #pragma unroll
            for(int j=0;j<4;j++) acc[mt][nt][j]=0.f;

    const int NK = KDIM/16;
    // prologue: stage 0
    #pragma unroll
    for(int i=0;i<4;i++){
        int q = tid + i*256;               // A: 1024 chunks
        cpa16(&As[0][(q>>2)*24 + (q&3)*4], A + (rowBase + (q>>2))*KDIM + (q&3)*4);
    }
    cpa16(&Bs[0][(tid>>2)*24 + (tid&3)*4], Wt + (colBase + (tid>>2))*KDIM + (tid&3)*4);
    asm volatile("cp.async.commit_group;");

    #pragma unroll 1
    for(int kt=0; kt<NK; kt++){
        int buf = kt&1;
        __syncthreads();                   // all warps done with buf (from kt-2)
        if(kt+1 < NK){
            #pragma unroll
            for(int i=0;i<4;i++){
                int q = tid + i*256;
                cpa16(&As[buf^1][(q>>2)*24 + (q&3)*4],
                      A + (rowBase + (q>>2))*KDIM + (kt+1)*16 + (q&3)*4);
            }
            cpa16(&Bs[buf^1][(tid>>2)*24 + (tid&3)*4],
                  Wt + (colBase + (tid>>2))*KDIM + (kt+1)*16 + (tid&3)*4);
            asm volatile("cp.async.commit_group;");
            asm volatile("cp.async.wait_group 1;");
        } else {
            asm volatile("cp.async.wait_group 0;");
        }
        __syncthreads();                   // stage kt visible

        #pragma unroll
        for(int ks=0;ks<2;ks++){
            unsigned af[2][4];
            #pragma unroll
            for(int mt=0;mt<2;mt++){
                int r = warp*32 + mt*16 + g;
                uint2 lo = *(const uint2*)&As[buf][ r   *24 + ks*8 + 2*c];
                uint2 hi = *(const uint2*)&As[buf][(r+8)*24 + ks*8 + 2*c];
                af[mt][0]=lo.x; af[mt][2]=lo.y; af[mt][1]=hi.x; af[mt][3]=hi.y;
            }
            #pragma unroll
            for(int nt=0;nt<8;nt++){
                uint2 bb = *(const uint2*)&Bs[buf][(nt*8+g)*24 + ks*8 + 2*c];
                mma8(acc[0][nt], af[0][0],af[0][1],af[0][2],af[0][3], bb.x,bb.y);
                mma8(acc[1][nt], af[1][0],af[1][1],af[1][2],af[1][3], bb.x,bb.y);
            }
        }
    }

    #pragma unroll
    for(int mt=0;mt<2;mt++)
    #pragma unroll
    for(int i=0;i<2;i++){
        int r = rowBase + warp*32 + mt*16 + g + i*8;
        #pragma unroll
        for(int nt=0;nt<8;nt++){
            int col0 = colBase + nt*8 + 2*c;
            float v0 = acc[mt][nt][i*2+0] + bias[col0];
            float v1 = acc[mt][nt][i*2+1] + bias[col0+1];
            if(MODE==0){
                int b = r>>11, n = r&2047;
                int h = col0>>5, d = col0&31;
                float2 o; o.x = v0; o.y = v1;
                *(float2*)&out[((b*HH+h)*NN + n)*32 + d] = o;
            } else if(MODE==1){
                int b = r>>11, n = r&2047;
                int np = (n & ~7) | phi8(n&7);
                int h = col0>>5;
                int d0 = col0&31, d1 = d0+1;
                out[((b*HH+h)*NN + np)*32 + ((d0&24)|phi8(d0&7))] = f2tff(v0);
                out[((b*HH+h)*NN + np)*32 + ((d1&24)|phi8(d1&7))] = f2tff(v1);
            } else if(MODE==2){
                int b = r>>11, n = r&2047;
                int np = (n & ~7) | phi8(n&7);
                int h = col0>>5, d = col0&31;
                out[((b*HH+h)*32 + d  )*NN + np] = f2tff(v0);
                out[((b*HH+h)*32 + d+1)*NN + np] = f2tff(v1);
            } else if(MODE==3){
                float g0 = 0.5f*v0*(1.f+erff(v0*0.70710678118654752f));
                float g1 = 0.5f*v1*(1.f+erff(v1*0.70710678118654752f));
                out[r*NDIM + ((col0&~7)|phi8(col0&7))]         = f2tff(g0);
                out[r*NDIM + (((col0+1)&~7)|phi8((col0+1)&7))] = f2tff(g1);
            } else {
                float2 rr = *(const float2*)&resid[r*NDIM + col0];
                float2 o; o.x = rr.x+v0; o.y = rr.y+v1;
                *(float2*)&out[r*NDIM + col0] = o;
            }
        }
    }
}

// ---------------- tensor-core flash attention + per-head Q residual ----------------
__global__ __launch_bounds__(256)
void attn_tc(const float* __restrict__ Q, const float* __restrict__ K,
             const float* __restrict__ V, float* __restrict__ O)
{
    __shared__ float Ks[2][64*40];
    __shared__ float Vs[2][32*72];
    const int tid  = threadIdx.x;
    const int warp = tid>>5, lane = tid&31, g = lane>>2, c = lane&3;
    const int bh = blockIdx.y;
    const int b  = bh>>3, h = bh&7;
    const int qbase = blockIdx.x*128;
    const float* Qg = Q + (bh*NN + qbase)*32;
    const float* Kg = K + (long)bh*NN*32;
    const float* Vg = V + (long)bh*32*NN;

    // Q fragments scaled by log2(e)/16 so softmax uses a single exp2
    const float QS = 0.0625f * 1.44269504088896341f;
    unsigned qf[4][4];
    #pragma unroll
    for(int ks=0;ks<4;ks++){
        int r0 = warp*16 + g;
        qf[ks][0] = f2tf(Qg[ r0   *32 + ks*8 + c    ] * QS);
        qf[ks][1] = f2tf(Qg[(r0+8)*32 + ks*8 + c    ] * QS);
        qf[ks][2] = f2tf(Qg[ r0   *32 + ks*8 + c + 4] * QS);
        qf[ks][3] = f2tf(Qg[(r0+8)*32 + ks*8 + c + 4] * QS);
    }

    float oacc[4][4];
    #pragma unroll
    for(int nt=0;nt<4;nt++)
        #pragma unroll
        for(int j=0;j<4;j++) oacc[nt][j]=0.f;
    float l0 = 0.f, l1 = 0.f;

    #pragma unroll
    for(int i=0;i<2;i++){
        int idx = tid + i*256;
        cpa16(&Ks[0][(idx>>3)*40 + (idx&7)*4], Kg + (idx>>3)*32 + (idx&7)*4);
    }
    #pragma unroll
    for(int i=0;i<2;i++){
        int idx = tid + i*256;
        cpa16(&Vs[0][(idx>>4)*72 + (idx&15)*4], Vg + (idx>>4)*NN + (idx&15)*4);
    }
    asm volatile("cp.async.commit_group;");

    #pragma unroll 1
    for(int kt=0; kt<NN/64; kt++){
        int buf = kt&1;
        __syncthreads();
        if(kt+1 < NN/64){
            #pragma unroll
            for(int i=0;i<2;i++){
                int idx = tid + i*256;
                cpa16(&Ks[buf^1][(idx>>3)*40 + (idx&7)*4],
                      Kg + ((kt+1)*64 + (idx>>3))*32 + (idx&7)*4);
            }
            #pragma unroll
            for(int i=0;i<2;i++){
                int idx = tid + i*256;
                cpa16(&Vs[buf^1][(idx>>4)*72 + (idx&15)*4],
                      Vg + (idx>>4)*NN + (kt+1)*64 + (idx&15)*4);
            }
            asm volatile("cp.async.commit_group;");
            asm volatile("cp.async.wait_group 1;");
        } else {
            asm volatile("cp.async.wait_group 0;");
        }
        __syncthreads();

        float sv[8][4];
        #pragma unroll
        for(int nt=0;nt<8;nt++)
            #pragma unroll
            for(int j=0;j<4;j++) sv[nt][j]=0.f;
        #pragma unroll
        for(int ks=0;ks<4;ks++){
            #pragma unroll
            for(int nt=0;nt<8;nt++){
                float2 bp = *(const float2*)&Ks[buf][(nt*8+g)*40 + ks*8 + 2*c];
                mma8(sv[nt], qf[ks][0],qf[ks][1],qf[ks][2],qf[ks][3],
                     __float_as_uint(bp.x), __float_as_uint(bp.y));
            }
        }
        #pragma unroll
        for(int nt=0;nt<8;nt++){
            #pragma unroll
            for(int j=0;j<4;j++){
                float p = f2tff(exp2f(sv[nt][j]));
                sv[nt][j] = p;
                if(j<2) l0 += p; else l1 += p;
            }
        }
        #pragma unroll
        for(int ks=0;ks<8;ks++){
            #pragma unroll
            for(int nt=0;nt<4;nt++){
                float2 bp = *(const float2*)&Vs[buf][(nt*8+g)*72 + ks*8 + 2*c];
                mma8(oacc[nt],
                     __float_as_uint(sv[ks][0]), __float_as_uint(sv[ks][2]),
                     __float_as_uint(sv[ks][1]), __float_as_uint(sv[ks][3]),
                     __float_as_uint(bp.x), __float_as_uint(bp.y));
            }
        }
    }

    l0 += __shfl_xor_sync(0xffffffffu, l0, 1);
    l0 += __shfl_xor_sync(0xffffffffu, l0, 2);
    l1 += __shfl_xor_sync(0xffffffffu, l1, 1);
    l1 += __shfl_xor_sync(0xffffffffu, l1, 2);
    float inv0 = 1.f/l0, inv1 = 1.f/l1;

    #pragma unroll
    for(int i=0;i<2;i++){
        int rloc = warp*16 + g + i*8;
        int row  = qbase + rloc;
        float inv = (i==0) ? inv0 : inv1;
        #pragma unroll
        for(int nt=0;nt<4;nt++){
            int col = nt*8 + 2*c;
            float q0 = Qg[rloc*32 + col];
            float q1 = Qg[rloc*32 + col + 1];
            float2 o;
            o.x = q0 + oacc[nt][i*2+0]*inv;
            o.y = q1 + oacc[nt][i*2+1]*inv;
            *(float2*)&O[((long)b*NN + row)*DV + h*32 + col] = o;
        }
    }
}

// ---------------- launch ----------------
extern "C" void kernel_launch(void* const* d_in, const int* /*in_sizes*/, int /*n_in*/,
                              void* d_out, int /*out_size*/)
{
    const float* x     = (const float*)d_in[0];
    const float* y     = (const float*)d_in[1];
    const float* Wq    = (const float*)d_in[2];
    const float* bq    = (const float*)d_in[3];
    const float* Wk    = (const float*)d_in[4];
    const float* bk    = (const float*)d_in[5];
    const float* Wv    = (const float*)d_in[6];
    const float* bv    = (const float*)d_in[7];
    const float* W1    = (const float*)d_in[8];
    const float* b1    = (const float*)d_in[9];
    const float* W2    = (const float*)d_in[10];
    const float* b2    = (const float*)d_in[11];
    const float* ln0_g = (const float*)d_in[12];
    const float* ln0_b = (const float*)d_in[13];
    const float* ln1_g = (const float*)d_in[14];
    const float* ln1_b = (const float*)d_in[15];
    float* out = (float*)d_out;

    float *xn,*yr,*Q,*K,*V,*O,*On,*H1,*wq,*wk,*wv,*w1,*w2;
    cudaGetSymbolAddress((void**)&xn, g_xn);
    cudaGetSymbolAddress((void**)&yr, g_yr);
    cudaGetSymbolAddress((void**)&Q,  g_Q);
    cudaGetSymbolAddress((void**)&K,  g_K);
    cudaGetSymbolAddress((void**)&V,  g_V);
    cudaGetSymbolAddress((void**)&O,  g_O);
    cudaGetSymbolAddress((void**)&On, g_On);
    cudaGetSymbolAddress((void**)&H1, g_H1);
    cudaGetSymbolAddress((void**)&wq, g_Wq);
    cudaGetSymbolAddress((void**)&wk, g_Wk);
    cudaGetSymbolAddress((void**)&wv, g_Wv);
    cudaGetSymbolAddress((void**)&w1, g_W1);
    cudaGetSymbolAddress((void**)&w2, g_W2);

    wprep<<<DV*DV/256, 256>>>(Wq, wq, DV, DV);
    wprep<<<DV*DV/256, 256>>>(Wk, wk, DV, DV);
    wprep<<<DV*DV/256, 256>>>(Wv, wv, DV, DV);
    wprep<<<DV*DFF/256, 256>>>(W1, w1, DV, DFF);
    wprep<<<DFF*DV/256, 256>>>(W2, w2, DFF, DV);
    yprep<<<MROWS*DV/256, 256>>>(y, yr);

    ln_kernel<1><<<MROWS, 256>>>(x, xn, ln0_g, ln0_b);
    gemm_tc<256,256,0><<<dim3(4, 64), 256>>>(xn, wq, bq, Q,  nullptr);
    gemm_tc<256,256,1><<<dim3(4, 64), 256>>>(yr, wk, bk, K,  nullptr);
    gemm_tc<256,256,2><<<dim3(4, 64), 256>>>(yr, wv, bv, V,  nullptr);
    attn_tc<<<dim3(NN/128, BB*HH), 256>>>(Q, K, V, O);
    ln_kernel<1><<<MROWS, 256>>>(O, On, ln1_g, ln1_b);
    gemm_tc<256,512,3><<<dim3(8, 64), 256>>>(On, w1, b1, H1, nullptr);
    gemm_tc<512,256,4><<<dim3(4, 64), 256>>>(H1, w2, b2, out, O);
}

// round 9
// speedup vs baseline: 3.5202x; 1.0319x over previous
#include <cuda_runtime.h>
#include <math.h>

#define BB 8
#define NN 2048
#define DV 256
#define HH 8
#define DFF 512
#define MROWS (BB*NN)

// ---------------- scratch ----------------
__device__ float g_xn[MROWS*DV];    // ln0 out, rounded+phi-permuted k
__device__ float g_yr[MROWS*DV];    // y rounded+phi-permuted k
__device__ float g_Q [MROWS*DV];    // [B,H,N,32] fp32 exact
__device__ float g_K [MROWS*DV];    // [B,H,N,32] token+d phi-permuted, rounded
__device__ float g_V [MROWS*DV];    // [B,H,32,N] token phi-permuted, rounded
__device__ float g_O [MROWS*DV];    // exact
__device__ float g_On[MROWS*DV];    // ln1 out, rounded+permuted
__device__ float g_H1[MROWS*DFF];   // gelu out, rounded+permuted
__device__ float g_Wq[DV*DV];       // Wt[n][kphys] rounded
__device__ float g_Wk[DV*DV];
__device__ float g_Wv[DV*DV];
__device__ float g_W1[DV*DFF];
__device__ float g_W2[DFF*DV];

__device__ __forceinline__ unsigned f2tf(float x){
    unsigned r; asm("cvt.rna.tf32.f32 %0, %1;" : "=r"(r) : "f"(x)); return r;
}
__device__ __forceinline__ float f2tff(float x){ return __uint_as_float(f2tf(x)); }
__device__ __forceinline__ float fast_ex2(float x){
    float r; asm("ex2.approx.ftz.f32 %0, %1;" : "=f"(r) : "f"(x)); return r;
}
__device__ __forceinline__ void mma8(float* c, unsigned a0,unsigned a1,unsigned a2,unsigned a3,
                                     unsigned b0,unsigned b1){
    asm volatile("mma.sync.aligned.m16n8k8.row.col.f32.tf32.tf32.f32 "
      "{%0,%1,%2,%3}, {%4,%5,%6,%7}, {%8,%9}, {%0,%1,%2,%3};"
      : "+f"(c[0]),"+f"(c[1]),"+f"(c[2]),"+f"(c[3])
      : "r"(a0),"r"(a1),"r"(a2),"r"(a3),"r"(b0),"r"(b1));
}
__device__ __forceinline__ int phi8(int v){ return ((v&3)<<1)|((v>>2)&1); }
__device__ __forceinline__ void cpa16(void* smem, const void* gmem){
    unsigned s = (unsigned)__cvta_generic_to_shared(smem);
    asm volatile("cp.async.cg.shared.global [%0], [%1], 16;" :: "r"(s), "l"(gmem));
}

// ---------------- prep: three 256x256 weights -> Wt[n][kphys], rounded ----------------
__global__ __launch_bounds__(256)
void wprep3(const float* __restrict__ Wa, const float* __restrict__ Wb,
            const float* __restrict__ Wc,
            float* __restrict__ Ta, float* __restrict__ Tb, float* __restrict__ Tc){
    const float* W = (blockIdx.y==0)?Wa:(blockIdx.y==1)?Wb:Wc;
    float*      T = (blockIdx.y==0)?Ta:(blockIdx.y==1)?Tb:Tc;
    int i = blockIdx.x*256 + threadIdx.x;
    int k = i>>8, n = i&255;
    T[n*DV + ((k&~7)|phi8(k&7))] = f2tff(W[i]);
}
__global__ __launch_bounds__(256)
void wprep(const float* __restrict__ W, float* __restrict__ Wt, int KD, int ND){
    int i = blockIdx.x*256 + threadIdx.x;
    if(i >= KD*ND) return;
    int k = i/ND, n = i - k*ND;
    Wt[n*KD + ((k&~7)|phi8(k&7))] = f2tff(W[i]);
}
__global__ __launch_bounds__(256)
void yprep(const float* __restrict__ y, float* __restrict__ yr){
    int i = blockIdx.x*256 + threadIdx.x;
    yr[(i&~7)|phi8(i&7)] = f2tff(y[i]);
}

// ---------------- layernorm (D=256); PERM=1 -> rounded + phi-permuted out ---------------
template<int PERM>
__global__ __launch_bounds__(256)
void ln_kernel(const float* __restrict__ src, float* __restrict__ dst,
               const float* __restrict__ gamma, const float* __restrict__ beta)
{
    int row = blockIdx.x, tid = threadIdx.x;
    float v = src[row*256 + tid];
    float s = v, s2 = v*v;
    #pragma unroll
    for (int o = 16; o; o >>= 1) {
        s  += __shfl_xor_sync(0xffffffffu, s,  o);
        s2 += __shfl_xor_sync(0xffffffffu, s2, o);
    }
    __shared__ float ws[8], ws2[8];
    int w = tid >> 5, ln = tid & 31;
    if (ln == 0) { ws[w] = s; ws2[w] = s2; }
    __syncthreads();
    if (w == 0) {
        float a  = (ln < 8) ? ws[ln]  : 0.f;
        float b  = (ln < 8) ? ws2[ln] : 0.f;
        #pragma unroll
        for (int o = 4; o; o >>= 1) {
            a += __shfl_xor_sync(0xffffffffu, a, o);
            b += __shfl_xor_sync(0xffffffffu, b, o);
        }
        if (ln == 0) { ws[0] = a; ws2[0] = b; }
    }
    __syncthreads();
    float mu  = ws[0]*(1.f/256.f);
    float var = ws2[0]*(1.f/256.f) - mu*mu;
    float inv = rsqrtf(var + 1e-5f);
    float r = (v - mu)*inv*gamma[tid] + beta[tid];
    if(PERM) dst[row*256 + ((tid&~7)|phi8(tid&7))] = f2tff(r);
    else     dst[row*256 + tid] = r;
}

// ---------------- tensor-core GEMM, pre-rounded operands, cp.async pipeline -------------
template<int KDIM,int NDIM,int MODE>
__global__ __launch_bounds__(256)
void gemm_tc(const float* __restrict__ A, const float* __restrict__ Wt,
             const float* __restrict__ bias, float* __restrict__ out,
             const float* __restrict__ resid)
{
    __shared__ unsigned As[2][256*24];
    __shared__ unsigned Bs[2][64*24];
    const int tid  = threadIdx.x;
    const int warp = tid>>5, lane = tid&31, g = lane>>2, c = lane&3;
    const int rowBase = blockIdx.y*256;
    const int colBase = blockIdx.x*64;

    float acc[2][8][4];
    #pragma unroll
    for(int mt=0;mt<2;mt++)
        #pragma unroll
        for(int nt=0;nt<8;nt++)
            #pragma unroll
            for(int j=0;j<4;j++) acc[mt][nt][j]=0.f;

    const int NK = KDIM/16;
    #pragma unroll
    for(int i=0;i<4;i++){
        int q = tid + i*256;
        cpa16(&As[0][(q>>2)*24 + (q&3)*4], A + (rowBase + (q>>2))*KDIM + (q&3)*4);
    }
    cpa16(&Bs[0][(tid>>2)*24 + (tid&3)*4], Wt + (colBase + (tid>>2))*KDIM + (tid&3)*4);
    asm volatile("cp.async.commit_group;");

    #pragma unroll 1
    for(int kt=0; kt<NK; kt++){
        int buf = kt&1;
        __syncthreads();
        if(kt+1 < NK){
            #pragma unroll
            for(int i=0;i<4;i++){
                int q = tid + i*256;
                cpa16(&As[buf^1][(q>>2)*24 + (q&3)*4],
                      A + (rowBase + (q>>2))*KDIM + (kt+1)*16 + (q&3)*4);
            }
            cpa16(&Bs[buf^1][(tid>>2)*24 + (tid&3)*4],
                  Wt + (colBase + (tid>>2))*KDIM + (kt+1)*16 + (tid&3)*4);
            asm volatile("cp.async.commit_group;");
            asm volatile("cp.async.wait_group 1;");
        } else {
            asm volatile("cp.async.wait_group 0;");
        }
        __syncthreads();

        #pragma unroll
        for(int ks=0;ks<2;ks++){
            unsigned af[2][4];
            #pragma unroll
            for(int mt=0;mt<2;mt++){
                int r = warp*32 + mt*16 + g;
                uint2 lo = *(const uint2*)&As[buf][ r   *24 + ks*8 + 2*c];
                uint2 hi = *(const uint2*)&As[buf][(r+8)*24 + ks*8 + 2*c];
                af[mt][0]=lo.x; af[mt][2]=lo.y; af[mt][1]=hi.x; af[mt][3]=hi.y;
            }
            #pragma unroll
            for(int nt=0;nt<8;nt++){
                uint2 bb = *(const uint2*)&Bs[buf][(nt*8+g)*24 + ks*8 + 2*c];
                mma8(acc[0][nt], af[0][0],af[0][1],af[0][2],af[0][3], bb.x,bb.y);
                mma8(acc[1][nt], af[1][0],af[1][1],af[1][2],af[1][3], bb.x,bb.y);
            }
        }
    }

    #pragma unroll
    for(int mt=0;mt<2;mt++)
    #pragma unroll
    for(int i=0;i<2;i++){
        int r = rowBase + warp*32 + mt*16 + g + i*8;
        #pragma unroll
        for(int nt=0;nt<8;nt++){
            int col0 = colBase + nt*8 + 2*c;
            float v0 = acc[mt][nt][i*2+0] + bias[col0];
            float v1 = acc[mt][nt][i*2+1] + bias[col0+1];
            if(MODE==0){
                int b = r>>11, n = r&2047;
                int h = col0>>5, d = col0&31;
                float2 o; o.x = v0; o.y = v1;
                *(float2*)&out[((b*HH+h)*NN + n)*32 + d] = o;
            } else if(MODE==1){
                int b = r>>11, n = r&2047;
                int np = (n & ~7) | phi8(n&7);
                int h = col0>>5;
                int d0 = col0&31, d1 = d0+1;
                out[((b*HH+h)*NN + np)*32 + ((d0&24)|phi8(d0&7))] = f2tff(v0);
                out[((b*HH+h)*NN + np)*32 + ((d1&24)|phi8(d1&7))] = f2tff(v1);
            } else if(MODE==2){
                int b = r>>11, n = r&2047;
                int np = (n & ~7) | phi8(n&7);
                int h = col0>>5, d = col0&31;
                out[((b*HH+h)*32 + d  )*NN + np] = f2tff(v0);
                out[((b*HH+h)*32 + d+1)*NN + np] = f2tff(v1);
            } else if(MODE==3){
                float g0 = 0.5f*v0*(1.f+erff(v0*0.70710678118654752f));
                float g1 = 0.5f*v1*(1.f+erff(v1*0.70710678118654752f));
                out[r*NDIM + ((col0&~7)|phi8(col0&7))]         = f2tff(g0);
                out[r*NDIM + (((col0+1)&~7)|phi8((col0+1)&7))] = f2tff(g1);
            } else {
                float2 rr = *(const float2*)&resid[r*NDIM + col0];
                float2 o; o.x = rr.x+v0; o.y = rr.y+v1;
                *(float2*)&out[r*NDIM + col0] = o;
            }
        }
    }
}

// ---------------- tensor-core flash attention + per-head Q residual ----------------
__global__ __launch_bounds__(256,2)
void attn_tc(const float* __restrict__ Q, const float* __restrict__ K,
             const float* __restrict__ V, float* __restrict__ O)
{
    __shared__ float Ks[2][64*40];
    __shared__ float Vs[2][32*72];
    const int tid  = threadIdx.x;
    const int warp = tid>>5, lane = tid&31, g = lane>>2, c = lane&3;
    const int bh = blockIdx.y;
    const int b  = bh>>3, h = bh&7;
    const int qbase = blockIdx.x*128;
    const float* Qg = Q + (bh*NN + qbase)*32;
    const float* Kg = K + (long)bh*NN*32;
    const float* Vg = V + (long)bh*32*NN;

    const float QS = 0.0625f * 1.44269504088896341f;   // log2(e)/16
    unsigned qf[4][4];
    #pragma unroll
    for(int ks=0;ks<4;ks++){
        int r0 = warp*16 + g;
        qf[ks][0] = f2tf(Qg[ r0   *32 + ks*8 + c    ] * QS);
        qf[ks][1] = f2tf(Qg[(r0+8)*32 + ks*8 + c    ] * QS);
        qf[ks][2] = f2tf(Qg[ r0   *32 + ks*8 + c + 4] * QS);
        qf[ks][3] = f2tf(Qg[(r0+8)*32 + ks*8 + c + 4] * QS);
    }

    float oacc[4][4];
    #pragma unroll
    for(int nt=0;nt<4;nt++)
        #pragma unroll
        for(int j=0;j<4;j++) oacc[nt][j]=0.f;
    float l0 = 0.f, l1 = 0.f;

    #pragma unroll
    for(int i=0;i<2;i++){
        int idx = tid + i*256;
        cpa16(&Ks[0][(idx>>3)*40 + (idx&7)*4], Kg + (idx>>3)*32 + (idx&7)*4);
    }
    #pragma unroll
    for(int i=0;i<2;i++){
        int idx = tid + i*256;
        cpa16(&Vs[0][(idx>>4)*72 + (idx&15)*4], Vg + (idx>>4)*NN + (idx&15)*4);
    }
    asm volatile("cp.async.commit_group;");

    #pragma unroll 1
    for(int kt=0; kt<NN/64; kt++){
        int buf = kt&1;
        __syncthreads();
        if(kt+1 < NN/64){
            #pragma unroll
            for(int i=0;i<2;i++){
                int idx = tid + i*256;
                cpa16(&Ks[buf^1][(idx>>3)*40 + (idx&7)*4],
                      Kg + ((kt+1)*64 + (idx>>3))*32 + (idx&7)*4);
            }
            #pragma unroll
            for(int i=0;i<2;i++){
                int idx = tid + i*256;
                cpa16(&Vs[buf^1][(idx>>4)*72 + (idx&15)*4],
                      Vg + (idx>>4)*NN + (kt+1)*64 + (idx&15)*4);
            }
            asm volatile("cp.async.commit_group;");
            asm volatile("cp.async.wait_group 1;");
        } else {
            asm volatile("cp.async.wait_group 0;");
        }
        __syncthreads();

        float sv[8][4];
        #pragma unroll
        for(int nt=0;nt<8;nt++)
            #pragma unroll
            for(int j=0;j<4;j++) sv[nt][j]=0.f;
        #pragma unroll
        for(int ks=0;ks<4;ks++){
            #pragma unroll
            for(int nt=0;nt<8;nt++){
                float2 bp = *(const float2*)&Ks[buf][(nt*8+g)*40 + ks*8 + 2*c];
                mma8(sv[nt], qf[ks][0],qf[ks][1],qf[ks][2],qf[ks][3],
                     __float_as_uint(bp.x), __float_as_uint(bp.y));
            }
        }
        #pragma unroll
        for(int nt=0;nt<8;nt++){
            #pragma unroll
            for(int j=0;j<4;j++){
                float p = f2tff(fast_ex2(sv[nt][j]));
                sv[nt][j] = p;
                if(j<2) l0 += p; else l1 += p;
            }
        }
        #pragma unroll
        for(int ks=0;ks<8;ks++){
            #pragma unroll
            for(int nt=0;nt<4;nt++){
                float2 bp = *(const float2*)&Vs[buf][(nt*8+g)*72 + ks*8 + 2*c];
                mma8(oacc[nt],
                     __float_as_uint(sv[ks][0]), __float_as_uint(sv[ks][2]),
                     __float_as_uint(sv[ks][1]), __float_as_uint(sv[ks][3]),
                     __float_as_uint(bp.x), __float_as_uint(bp.y));
            }
        }
    }

    l0 += __shfl_xor_sync(0xffffffffu, l0, 1);
    l0 += __shfl_xor_sync(0xffffffffu, l0, 2);
    l1 += __shfl_xor_sync(0xffffffffu, l1, 1);
    l1 += __shfl_xor_sync(0xffffffffu, l1, 2);
    float inv0 = 1.f/l0, inv1 = 1.f/l1;

    #pragma unroll
    for(int i=0;i<2;i++){
        int rloc = warp*16 + g + i*8;
        int row  = qbase + rloc;
        float inv = (i==0) ? inv0 : inv1;
        #pragma unroll
        for(int nt=0;nt<4;nt++){
            int col = nt*8 + 2*c;
            float q0 = Qg[rloc*32 + col];
            float q1 = Qg[rloc*32 + col + 1];
            float2 o;
            o.x = q0 + oacc[nt][i*2+0]*inv;
            o.y = q1 + oacc[nt][i*2+1]*inv;
            *(float2*)&O[((long)b*NN + row)*DV + h*32 + col] = o;
        }
    }
}

// ---------------- launch ----------------
extern "C" void kernel_launch(void* const* d_in, const int* /*in_sizes*/, int /*n_in*/,
                              void* d_out, int /*out_size*/)
{
    const float* x     = (const float*)d_in[0];
    const float* y     = (const float*)d_in[1];
    const float* Wq    = (const float*)d_in[2];
    const float* bq    = (const float*)d_in[3];
    const float* Wk    = (const float*)d_in[4];
    const float* bk    = (const float*)d_in[5];
    const float* Wv    = (const float*)d_in[6];
    const float* bv    = (const float*)d_in[7];
    const float* W1    = (const float*)d_in[8];
    const float* b1    = (const float*)d_in[9];
    const float* W2    = (const float*)d_in[10];
    const float* b2    = (const float*)d_in[11];
    const float* ln0_g = (const float*)d_in[12];
    const float* ln0_b = (const float*)d_in[13];
    const float* ln1_g = (const float*)d_in[14];
    const float* ln1_b = (const float*)d_in[15];
    float* out = (float*)d_out;

    float *xn,*yr,*Q,*K,*V,*O,*On,*H1,*wq,*wk,*wv,*w1,*w2;
    cudaGetSymbolAddress((void**)&xn, g_xn);
    cudaGetSymbolAddress((void**)&yr, g_yr);
    cudaGetSymbolAddress((void**)&Q,  g_Q);
    cudaGetSymbolAddress((void**)&K,  g_K);
    cudaGetSymbolAddress((void**)&V,  g_V);
    cudaGetSymbolAddress((void**)&O,  g_O);
    cudaGetSymbolAddress((void**)&On, g_On);
    cudaGetSymbolAddress((void**)&H1, g_H1);
    cudaGetSymbolAddress((void**)&wq, g_Wq);
    cudaGetSymbolAddress((void**)&wk, g_Wk);
    cudaGetSymbolAddress((void**)&wv, g_Wv);
    cudaGetSymbolAddress((void**)&w1, g_W1);
    cudaGetSymbolAddress((void**)&w2, g_W2);

    wprep3<<<dim3(DV*DV/256, 3), 256>>>(Wq, Wk, Wv, wq, wk, wv);
    wprep<<<DV*DFF/256, 256>>>(W1, w1, DV, DFF);
    wprep<<<DFF*DV/256, 256>>>(W2, w2, DFF, DV);
    yprep<<<MROWS*DV/256, 256>>>(y, yr);

    ln_kernel<1><<<MROWS, 256>>>(x, xn, ln0_g, ln0_b);
    gemm_tc<256,256,0><<<dim3(4, 64), 256>>>(xn, wq, bq, Q,  nullptr);
    gemm_tc<256,256,1><<<dim3(4, 64), 256>>>(yr, wk, bk, K,  nullptr);
    gemm_tc<256,256,2><<<dim3(4, 64), 256>>>(yr, wv, bv, V,  nullptr);
    attn_tc<<<dim3(NN/128, BB*HH), 256>>>(Q, K, V, O);
    ln_kernel<1><<<MROWS, 256>>>(O, On, ln1_g, ln1_b);
    gemm_tc<256,512,3><<<dim3(8, 64), 256>>>(On, w1, b1, H1, nullptr);
    gemm_tc<512,256,4><<<dim3(4, 64), 256>>>(H1, w2, b2, out, O);
}

// round 10
// speedup vs baseline: 5.0763x; 1.4420x over previous
#include <cuda_runtime.h>
#include <cuda_fp16.h>
#include <math.h>

#define BB 8
#define NN 2048
#define DV 256
#define HH 8
#define DFF 512
#define MROWS (BB*NN)

// ---------------- scratch ----------------
__device__ float  g_xn[MROWS*DV];    // ln0 out, rounded+phi-permuted k
__device__ float  g_yr[MROWS*DV];    // y rounded+phi-permuted k
__device__ float  g_Q [MROWS*DV];    // [B,H,N,32] fp32 exact
__device__ __half g_K [MROWS*DV];    // [B,H,N,32] d quad-interleaved, fp16
__device__ __half g_V [MROWS*DV];    // [B,H,32,N] key quad-interleaved, fp16
__device__ float  g_O [MROWS*DV];    // exact
__device__ float  g_On[MROWS*DV];    // ln1 out, rounded+permuted
__device__ float  g_H1[MROWS*DFF];   // gelu out, rounded+permuted
__device__ float  g_Wq[DV*DV];       // Wt[n][kphys] rounded
__device__ float  g_Wk[DV*DV];
__device__ float  g_Wv[DV*DV];
__device__ float  g_W1[DV*DFF];
__device__ float  g_W2[DFF*DV];

__device__ __forceinline__ unsigned f2tf(float x){
    unsigned r; asm("cvt.rna.tf32.f32 %0, %1;" : "=r"(r) : "f"(x)); return r;
}
__device__ __forceinline__ float f2tff(float x){ return __uint_as_float(f2tf(x)); }
__device__ __forceinline__ unsigned h2u(float lo, float hi){
    unsigned r; asm("cvt.rn.f16x2.f32 %0, %1, %2;" : "=r"(r) : "f"(hi), "f"(lo)); return r;
}
__device__ __forceinline__ unsigned ex2h2(unsigned x){
    unsigned r; asm("ex2.approx.f16x2 %0, %1;" : "=r"(r) : "r"(x)); return r;
}
__device__ __forceinline__ void mma8(float* c, unsigned a0,unsigned a1,unsigned a2,unsigned a3,
                                     unsigned b0,unsigned b1){
    asm volatile("mma.sync.aligned.m16n8k8.row.col.f32.tf32.tf32.f32 "
      "{%0,%1,%2,%3}, {%4,%5,%6,%7}, {%8,%9}, {%0,%1,%2,%3};"
      : "+f"(c[0]),"+f"(c[1]),"+f"(c[2]),"+f"(c[3])
      : "r"(a0),"r"(a1),"r"(a2),"r"(a3),"r"(b0),"r"(b1));
}
__device__ __forceinline__ void mmah(float* c, unsigned a0,unsigned a1,unsigned a2,unsigned a3,
                                     unsigned b0,unsigned b1){
    asm volatile("mma.sync.aligned.m16n8k16.row.col.f32.f16.f16.f32 "
      "{%0,%1,%2,%3}, {%4,%5,%6,%7}, {%8,%9}, {%0,%1,%2,%3};"
      : "+f"(c[0]),"+f"(c[1]),"+f"(c[2]),"+f"(c[3])
      : "r"(a0),"r"(a1),"r"(a2),"r"(a3),"r"(b0),"r"(b1));
}
__device__ __forceinline__ int phi8(int v){ return ((v&3)<<1)|((v>>2)&1); }
// quad-interleave within a 16-group: w=8*hi+2*cc+lo -> 4*cc+2*hi+lo
__device__ __forceinline__ int quad16(int w){
    return ((w&7)>>1)*4 + ((w>>3)&1)*2 + (w&1);
}
__device__ __forceinline__ void cpa16(void* smem, const void* gmem){
    unsigned s = (unsigned)__cvta_generic_to_shared(smem);
    asm volatile("cp.async.cg.shared.global [%0], [%1], 16;" :: "r"(s), "l"(gmem));
}

// ---------------- prep: smem-tiled transpose W[k][n] -> Wt[n][kphys], rounded ------------
template<int KD,int ND>
__global__ __launch_bounds__(256)
void wprep_t(const float* __restrict__ W, float* __restrict__ Wt){
    __shared__ float sm[32][33];
    const int tx = threadIdx.x&31, ty = threadIdx.x>>5;
    const int k0 = blockIdx.x*32, n0 = blockIdx.y*32;
    #pragma unroll
    for(int i=0;i<4;i++)
        sm[ty+8*i][tx] = f2tff(W[(k0+ty+8*i)*ND + n0+tx]);
    __syncthreads();
    const int INV8[8] = {0,4,1,5,2,6,3,7};
    #pragma unroll
    for(int i=0;i<4;i++){
        int n = n0 + ty + 8*i;
        int ksrc = (tx&~7) | INV8[tx&7];
        Wt[n*KD + k0 + tx] = sm[ksrc][ty+8*i];
    }
}
template<int KD,int ND>
__global__ __launch_bounds__(256)
void wprep_t3(const float* __restrict__ Wa, const float* __restrict__ Wb,
              const float* __restrict__ Wc,
              float* __restrict__ Ta, float* __restrict__ Tb, float* __restrict__ Tc){
    __shared__ float sm[32][33];
    const float* W = (blockIdx.z==0)?Wa:(blockIdx.z==1)?Wb:Wc;
    float*      T  = (blockIdx.z==0)?Ta:(blockIdx.z==1)?Tb:Tc;
    const int tx = threadIdx.x&31, ty = threadIdx.x>>5;
    const int k0 = blockIdx.x*32, n0 = blockIdx.y*32;
    #pragma unroll
    for(int i=0;i<4;i++)
        sm[ty+8*i][tx] = f2tff(W[(k0+ty+8*i)*ND + n0+tx]);
    __syncthreads();
    const int INV8[8] = {0,4,1,5,2,6,3,7};
    #pragma unroll
    for(int i=0;i<4;i++){
        int n = n0 + ty + 8*i;
        int ksrc = (tx&~7) | INV8[tx&7];
        T[n*KD + k0 + tx] = sm[ksrc][ty+8*i];
    }
}

// ---------------- prep: y -> rounded, phi-permuted, 8 elems/thread ----------------
__global__ __launch_bounds__(256)
void yprep8(const float* __restrict__ y, float* __restrict__ yr){
    int i = (blockIdx.x*256 + threadIdx.x)*8;
    float4 v0 = *(const float4*)(y+i);
    float4 v1 = *(const float4*)(y+i+4);
    float4 o0, o1;
    o0.x = f2tff(v0.x); o0.y = f2tff(v1.x); o0.z = f2tff(v0.y); o0.w = f2tff(v1.y);
    o1.x = f2tff(v0.z); o1.y = f2tff(v1.z); o1.z = f2tff(v0.w); o1.w = f2tff(v1.w);
    *(float4*)(yr+i)   = o0;
    *(float4*)(yr+i+4) = o1;
}

// ---------------- layernorm: warp per row, rounded + phi-permuted out ----------------
__global__ __launch_bounds__(256)
void ln_kernel(const float* __restrict__ src, float* __restrict__ dst,
               const float* __restrict__ gamma, const float* __restrict__ beta)
{
    const int lane = threadIdx.x&31, warp = threadIdx.x>>5;
    const int row = blockIdx.x*8 + warp;
    const float* p = src + row*256 + lane*8;
    float4 v0 = *(const float4*)p;
    float4 v1 = *(const float4*)(p+4);
    float s  = v0.x+v0.y+v0.z+v0.w + v1.x+v1.y+v1.z+v1.w;
    float s2 = v0.x*v0.x+v0.y*v0.y+v0.z*v0.z+v0.w*v0.w
             + v1.x*v1.x+v1.y*v1.y+v1.z*v1.z+v1.w*v1.w;
    #pragma unroll
    for(int o=16;o;o>>=1){
        s  += __shfl_xor_sync(0xffffffffu, s,  o);
        s2 += __shfl_xor_sync(0xffffffffu, s2, o);
    }
    float mu  = s*(1.f/256.f);
    float var = s2*(1.f/256.f) - mu*mu;
    float inv = rsqrtf(var + 1e-5f);
    float4 ga0 = *(const float4*)(gamma + lane*8);
    float4 ga1 = *(const float4*)(gamma + lane*8 + 4);
    float4 be0 = *(const float4*)(beta  + lane*8);
    float4 be1 = *(const float4*)(beta  + lane*8 + 4);
    float t[8];
    t[0]=(v0.x-mu)*inv*ga0.x+be0.x; t[1]=(v0.y-mu)*inv*ga0.y+be0.y;
    t[2]=(v0.z-mu)*inv*ga0.z+be0.z; t[3]=(v0.w-mu)*inv*ga0.w+be0.w;
    t[4]=(v1.x-mu)*inv*ga1.x+be1.x; t[5]=(v1.y-mu)*inv*ga1.y+be1.y;
    t[6]=(v1.z-mu)*inv*ga1.z+be1.z; t[7]=(v1.w-mu)*inv*ga1.w+be1.w;
    float4 o0, o1;   // phys p <- t[INV8[p]]
    o0.x=f2tff(t[0]); o0.y=f2tff(t[4]); o0.z=f2tff(t[1]); o0.w=f2tff(t[5]);
    o1.x=f2tff(t[2]); o1.y=f2tff(t[6]); o1.z=f2tff(t[3]); o1.w=f2tff(t[7]);
    *(float4*)(dst + row*256 + lane*8)     = o0;
    *(float4*)(dst + row*256 + lane*8 + 4) = o1;
}

// ---------------- tensor-core GEMM (tf32), pre-rounded operands ----------------
// MODE 0: Q exact fp32 | 1: K fp16 attn-layout | 2: V fp16 attn-layout
// MODE 3: gelu->H1 perm | 4: resid + out
template<int KDIM,int NDIM,int MODE>
__global__ __launch_bounds__(256)
void gemm_tc(const float* __restrict__ A, const float* __restrict__ Wt,
             const float* __restrict__ bias, float* __restrict__ out,
             const float* __restrict__ resid)
{
    __shared__ unsigned As[2][256*24];
    __shared__ unsigned Bs[2][64*24];
    const int tid  = threadIdx.x;
    const int warp = tid>>5, lane = tid&31, g = lane>>2, c = lane&3;
    const int rowBase = blockIdx.y*256;
    const int colBase = blockIdx.x*64;

    float acc[2][8][4];
    #pragma unroll
    for(int mt=0;mt<2;mt++)
        #pragma unroll
        for(int nt=0;nt<8;nt++)
            #pragma unroll
            for(int j=0;j<4;j++) acc[mt][nt][j]=0.f;

    const int NK = KDIM/16;
    #pragma unroll
    for(int i=0;i<4;i++){
        int q = tid + i*256;
        cpa16(&As[0][(q>>2)*24 + (q&3)*4], A + (rowBase + (q>>2))*KDIM + (q&3)*4);
    }
    cpa16(&Bs[0][(tid>>2)*24 + (tid&3)*4], Wt + (colBase + (tid>>2))*KDIM + (tid&3)*4);
    asm volatile("cp.async.commit_group;");

    #pragma unroll 1
    for(int kt=0; kt<NK; kt++){
        int buf = kt&1;
        __syncthreads();
        if(kt+1 < NK){
            #pragma unroll
            for(int i=0;i<4;i++){
                int q = tid + i*256;
                cpa16(&As[buf^1][(q>>2)*24 + (q&3)*4],
                      A + (rowBase + (q>>2))*KDIM + (kt+1)*16 + (q&3)*4);
            }
            cpa16(&Bs[buf^1][(tid>>2)*24 + (tid&3)*4],
                  Wt + (colBase + (tid>>2))*KDIM + (kt+1)*16 + (tid&3)*4);
            asm volatile("cp.async.commit_group;");
            asm volatile("cp.async.wait_group 1;");
        } else {
            asm volatile("cp.async.wait_group 0;");
        }
        __syncthreads();

        #pragma unroll
        for(int ks=0;ks<2;ks++){
            unsigned af[2][4];
            #pragma unroll
            for(int mt=0;mt<2;mt++){
                int r = warp*32 + mt*16 + g;
                uint2 lo = *(const uint2*)&As[buf][ r   *24 + ks*8 + 2*c];
                uint2 hi = *(const uint2*)&As[buf][(r+8)*24 + ks*8 + 2*c];
                af[mt][0]=lo.x; af[mt][2]=lo.y; af[mt][1]=hi.x; af[mt][3]=hi.y;
            }
            #pragma unroll
            for(int nt=0;nt<8;nt++){
                uint2 bb = *(const uint2*)&Bs[buf][(nt*8+g)*24 + ks*8 + 2*c];
                mma8(acc[0][nt], af[0][0],af[0][1],af[0][2],af[0][3], bb.x,bb.y);
                mma8(acc[1][nt], af[1][0],af[1][1],af[1][2],af[1][3], bb.x,bb.y);
            }
        }
    }

    #pragma unroll
    for(int mt=0;mt<2;mt++)
    #pragma unroll
    for(int i=0;i<2;i++){
        int r = rowBase + warp*32 + mt*16 + g + i*8;
        #pragma unroll
        for(int nt=0;nt<8;nt++){
            int col0 = colBase + nt*8 + 2*c;
            float v0 = acc[mt][nt][i*2+0] + bias[col0];
            float v1 = acc[mt][nt][i*2+1] + bias[col0+1];
            if(MODE==0){
                int b = r>>11, n = r&2047;
                int h = col0>>5, d = col0&31;
                float2 o; o.x = v0; o.y = v1;
                *(float2*)&out[((b*HH+h)*NN + n)*32 + d] = o;
            } else if(MODE==1){
                // K fp16: [bh][key][dphys], d quad-interleaved within 16-groups
                __half* oh = (__half*)out;
                int b = r>>11, n = r&2047;
                int h = col0>>5, d = col0&31;
                int dp = (d&~15) | quad16(d&15);    // d even -> dp even, d+1 -> dp+1
                __half2 hv = __floats2half2_rn(v0, v1);
                *(__half2*)&oh[((b*HH+h)*NN + n)*32 + dp] = hv;
            } else if(MODE==2){
                // V fp16: [bh][d][keyphys], key quad-interleaved within 16-groups
                __half* oh = (__half*)out;
                int b = r>>11, n = r&2047;
                int np = (n&~15) | quad16(n&15);
                int h = col0>>5, d = col0&31;
                oh[((b*HH+h)*32 + d  )*NN + np] = __float2half_rn(v0);
                oh[((b*HH+h)*32 + d+1)*NN + np] = __float2half_rn(v1);
            } else if(MODE==3){
                float g0 = 0.5f*v0*(1.f+erff(v0*0.70710678118654752f));
                float g1 = 0.5f*v1*(1.f+erff(v1*0.70710678118654752f));
                out[r*NDIM + ((col0&~7)|phi8(col0&7))]         = f2tff(g0);
                out[r*NDIM + (((col0+1)&~7)|phi8((col0+1)&7))] = f2tff(g1);
            } else {
                float2 rr = *(const float2*)&resid[r*NDIM + col0];
                float2 o; o.x = rr.x+v0; o.y = rr.y+v1;
                *(float2*)&out[r*NDIM + col0] = o;
            }
        }
    }
}

// ---------------- fp16 tensor-core flash attention + per-head Q residual ----------------
// grid (N/128, B*H), 8 warps; warp w owns q rows w*16..+15. Key tile 64, cp.async x2 buf.
// m16n8k16 fp16 mma; S C-frag packs directly into PV A-frag (half2).
// l (softmax denom) via extra mma against ones-column.
__global__ __launch_bounds__(256,2)
void attn_tc(const float* __restrict__ Q, const __half* __restrict__ K,
             const __half* __restrict__ V, float* __restrict__ O)
{
    __shared__ __align__(16) __half Ks[2][64*48];  // [key][dphys], stride 48 halfs (24 words)
    __shared__ __align__(16) __half Vs[2][32*80];  // [d][keyphys], stride 80 halfs (40 words)
    const int tid  = threadIdx.x;
    const int warp = tid>>5, lane = tid&31, g = lane>>2, c = lane&3;
    const int bh = blockIdx.y;
    const int b  = bh>>3, h = bh&7;
    const int qbase = blockIdx.x*128;
    const float*  Qg = Q + (bh*NN + qbase)*32;
    const __half* Kg = K + (long)bh*NN*32;
    const __half* Vg = V + (long)bh*32*NN;

    // Q fragments (fp16), scaled by log2(e)/16 so softmax is a single ex2
    const float QS = 0.0625f * 1.44269504088896341f;
    unsigned qf[2][4];
    {
        int r0 = warp*16 + g;
        #pragma unroll
        for(int kh=0;kh<2;kh++){
            int d0 = kh*16 + 2*c;
            qf[kh][0] = h2u(Qg[ r0   *32 + d0  ]*QS, Qg[ r0   *32 + d0+1]*QS);
            qf[kh][1] = h2u(Qg[(r0+8)*32 + d0  ]*QS, Qg[(r0+8)*32 + d0+1]*QS);
            qf[kh][2] = h2u(Qg[ r0   *32 + d0+8]*QS, Qg[ r0   *32 + d0+9]*QS);
            qf[kh][3] = h2u(Qg[(r0+8)*32 + d0+8]*QS, Qg[(r0+8)*32 + d0+9]*QS);
        }
    }

    float oacc[4][4];
    #pragma unroll
    for(int nt=0;nt<4;nt++)
        #pragma unroll
        for(int j=0;j<4;j++) oacc[nt][j]=0.f;
    float lacc[4] = {0.f,0.f,0.f,0.f};
    const unsigned ones = (g==0) ? 0x3C003C00u : 0u;   // half2(1,1) at col 0

    // prologue: tile 0
    cpa16(&Ks[0][(tid>>2)*48 + (tid&3)*8], Kg + (tid>>2)*32 + (tid&3)*8);
    cpa16(&Vs[0][(tid>>3)*80 + (tid&7)*8], Vg + (tid>>3)*NN + (tid&7)*8);
    asm volatile("cp.async.commit_group;");

    #pragma unroll 1
    for(int kt=0; kt<NN/64; kt++){
        int buf = kt&1;
        __syncthreads();
        if(kt+1 < NN/64){
            cpa16(&Ks[buf^1][(tid>>2)*48 + (tid&3)*8],
                  Kg + ((kt+1)*64 + (tid>>2))*32 + (tid&3)*8);
            cpa16(&Vs[buf^1][(tid>>3)*80 + (tid&7)*8],
                  Vg + (tid>>3)*NN + (kt+1)*64 + (tid&7)*8);
            asm volatile("cp.async.commit_group;");
            asm volatile("cp.async.wait_group 1;");
        } else {
            asm volatile("cp.async.wait_group 0;");
        }
        __syncthreads();

        // S = (Q*QS) K^T  (fp32 accum = base-2 logits)
        float sv[8][4];
        #pragma unroll
        for(int nt=0;nt<8;nt++)
            #pragma unroll
            for(int j=0;j<4;j++) sv[nt][j]=0.f;
        #pragma unroll
        for(int kh=0;kh<2;kh++){
            #pragma unroll
            for(int nt=0;nt<8;nt++){
                uint2 bb = *(const uint2*)&Ks[buf][(nt*8+g)*48 + kh*16 + 4*c];
                mmah(sv[nt], qf[kh][0],qf[kh][1],qf[kh][2],qf[kh][3], bb.x,bb.y);
            }
        }
        // p = 2^logit, packed fp16x2 (one MUFU op per 2 values)
        unsigned ph[8][2];
        #pragma unroll
        for(int nt=0;nt<8;nt++){
            ph[nt][0] = ex2h2(h2u(sv[nt][0], sv[nt][1]));
            ph[nt][1] = ex2h2(h2u(sv[nt][2], sv[nt][3]));
        }
        // O += P V ; l += P @ ones   (S C-frag == PV A-frag, zero shuffling)
        #pragma unroll
        for(int ks=0;ks<4;ks++){
            unsigned a0 = ph[2*ks][0], a1 = ph[2*ks][1];
            unsigned a2 = ph[2*ks+1][0], a3 = ph[2*ks+1][1];
            #pragma unroll
            for(int nt=0;nt<4;nt++){
                uint2 bb = *(const uint2*)&Vs[buf][(nt*8+g)*80 + ks*16 + 4*c];
                mmah(oacc[nt], a0,a1,a2,a3, bb.x,bb.y);
            }
            mmah(lacc, a0,a1,a2,a3, ones, ones);
        }
    }

    // l lives in col 0 (threads c==0); broadcast across the 4 lanes of each row
    float l0 = __shfl_sync(0xffffffffu, lacc[0], lane & ~3);
    float l1 = __shfl_sync(0xffffffffu, lacc[2], lane & ~3);
    float inv0 = 1.f/l0, inv1 = 1.f/l1;

    // epilogue: O = Q + (PV)/l  (exact fp32 Q residual)
    #pragma unroll
    for(int i=0;i<2;i++){
        int rloc = warp*16 + g + i*8;
        int row  = qbase + rloc;
        float inv = (i==0) ? inv0 : inv1;
        #pragma unroll
        for(int nt=0;nt<4;nt++){
            int col = nt*8 + 2*c;
            float q0 = Qg[rloc*32 + col];
            float q1 = Qg[rloc*32 + col + 1];
            float2 o;
            o.x = q0 + oacc[nt][i*2+0]*inv;
            o.y = q1 + oacc[nt][i*2+1]*inv;
            *(float2*)&O[((long)b*NN + row)*DV + h*32 + col] = o;
        }
    }
}

// ---------------- launch ----------------
extern "C" void kernel_launch(void* const* d_in, const int* /*in_sizes*/, int /*n_in*/,
                              void* d_out, int /*out_size*/)
{
    const float* x     = (const float*)d_in[0];
    const float* y     = (const float*)d_in[1];
    const float* Wq    = (const float*)d_in[2];
    const float* bq    = (const float*)d_in[3];
    const float* Wk    = (const float*)d_in[4];
    const float* bk    = (const float*)d_in[5];
    const float* Wv    = (const float*)d_in[6];
    const float* bv    = (const float*)d_in[7];
    const float* W1    = (const float*)d_in[8];
    const float* b1    = (const float*)d_in[9];
    const float* W2    = (const float*)d_in[10];
    const float* b2    = (const float*)d_in[11];
    const float* ln0_g = (const float*)d_in[12];
    const float* ln0_b = (const float*)d_in[13];
    const float* ln1_g = (const float*)d_in[14];
    const float* ln1_b = (const float*)d_in[15];
    float* out = (float*)d_out;

    float *xn,*yr,*Q,*O,*On,*H1,*wq,*wk,*wv,*w1,*w2;
    __half *K,*V;
    cudaGetSymbolAddress((void**)&xn, g_xn);
    cudaGetSymbolAddress((void**)&yr, g_yr);
    cudaGetSymbolAddress((void**)&Q,  g_Q);
    cudaGetSymbolAddress((void**)&K,  g_K);
    cudaGetSymbolAddress((void**)&V,  g_V);
    cudaGetSymbolAddress((void**)&O,  g_O);
    cudaGetSymbolAddress((void**)&On, g_On);
    cudaGetSymbolAddress((void**)&H1, g_H1);
    cudaGetSymbolAddress((void**)&wq, g_Wq);
    cudaGetSymbolAddress((void**)&wk, g_Wk);
    cudaGetSymbolAddress((void**)&wv, g_Wv);
    cudaGetSymbolAddress((void**)&w1, g_W1);
    cudaGetSymbolAddress((void**)&w2, g_W2);

    wprep_t3<DV,DV><<<dim3(8,8,3), 256>>>(Wq, Wk, Wv, wq, wk, wv);
    wprep_t<DV,DFF><<<dim3(8,16), 256>>>(W1, w1);
    wprep_t<DFF,DV><<<dim3(16,8), 256>>>(W2, w2);
    yprep8<<<MROWS*DV/2048, 256>>>(y, yr);

    ln_kernel<<<MROWS/8, 256>>>(x, xn, ln0_g, ln0_b);
    gemm_tc<256,256,0><<<dim3(4, 64), 256>>>(xn, wq, bq, Q,  nullptr);
    gemm_tc<256,256,1><<<dim3(4, 64), 256>>>(yr, wk, bk, (float*)K, nullptr);
    gemm_tc<256,256,2><<<dim3(4, 64), 256>>>(yr, wv, bv, (float*)V, nullptr);
    attn_tc<<<dim3(NN/128, BB*HH), 256>>>(Q, K, V, O);
    ln_kernel<<<MROWS/8, 256>>>(O, On, ln1_g, ln1_b);
    gemm_tc<256,512,3><<<dim3(8, 64), 256>>>(On, w1, b1, H1, nullptr);
    gemm_tc<512,256,4><<<dim3(4, 64), 256>>>(H1, w2, b2, out, O);
}

// round 11
// speedup vs baseline: 6.2877x; 1.2386x over previous
#include <cuda_runtime.h>
#include <cuda_fp16.h>
#include <math.h>

#define BB 8
#define NN 2048
#define DV 256
#define HH 8
#define DFF 512
#define MROWS (BB*NN)

// ---------------- scratch ----------------
__device__ __half g_xn[MROWS*DV];    // ln0 out, fp16, k quad16-interleaved
__device__ __half g_yr[MROWS*DV];    // y fp16, k quad16
__device__ float  g_Q [MROWS*DV];    // [B,H,N,32] fp32 exact
__device__ __half g_K [MROWS*DV];    // [B,H,N,32] d quad16, fp16
__device__ __half g_V [MROWS*DV];    // [B,H,32,N] key quad16, fp16
__device__ float  g_O [MROWS*DV];    // exact
__device__ __half g_On[MROWS*DV];    // ln1 out fp16 quad16
__device__ __half g_H1[MROWS*DFF];   // gelu out fp16 quad16
__device__ __half g_Wq[DV*DV];       // Wt[n][kphys] fp16
__device__ __half g_Wk[DV*DV];
__device__ __half g_Wv[DV*DV];
__device__ __half g_W1[DV*DFF];
__device__ __half g_W2[DFF*DV];

__device__ __forceinline__ unsigned h2u(float lo, float hi){
    unsigned r; asm("cvt.rn.f16x2.f32 %0, %1, %2;" : "=r"(r) : "f"(hi), "f"(lo)); return r;
}
__device__ __forceinline__ unsigned ex2h2(unsigned x){
    unsigned r; asm("ex2.approx.f16x2 %0, %1;" : "=r"(r) : "r"(x)); return r;
}
__device__ __forceinline__ void mmah(float* c, unsigned a0,unsigned a1,unsigned a2,unsigned a3,
                                     unsigned b0,unsigned b1){
    asm volatile("mma.sync.aligned.m16n8k16.row.col.f32.f16.f16.f32 "
      "{%0,%1,%2,%3}, {%4,%5,%6,%7}, {%8,%9}, {%0,%1,%2,%3};"
      : "+f"(c[0]),"+f"(c[1]),"+f"(c[2]),"+f"(c[3])
      : "r"(a0),"r"(a1),"r"(a2),"r"(a3),"r"(b0),"r"(b1));
}
// quad-interleave within a 16-group: w=8*hi+2*cc+lo -> 4*cc+2*hi+lo
__device__ __forceinline__ int quad16(int w){
    return ((w&7)>>1)*4 + ((w>>3)&1)*2 + (w&1);
}
__device__ __forceinline__ void cpa16(void* smem, const void* gmem){
    unsigned s = (unsigned)__cvta_generic_to_shared(smem);
    asm volatile("cp.async.cg.shared.global [%0], [%1], 16;" :: "r"(s), "l"(gmem));
}

// ---------------- prep: transpose W[k][n] -> Wt[n][kphys] fp16, k quad16 ----------------
__device__ __constant__ int INV16[16] = {0,1,8,9,2,3,10,11,4,5,12,13,6,7,14,15};

template<int KD,int ND>
__global__ __launch_bounds__(256)
void wprep_t(const float* __restrict__ W, __half* __restrict__ Wt){
    __shared__ float sm[32][33];
    const int tx = threadIdx.x&31, ty = threadIdx.x>>5;
    const int k0 = blockIdx.x*32, n0 = blockIdx.y*32;
    #pragma unroll
    for(int i=0;i<4;i++)
        sm[ty+8*i][tx] = W[(k0+ty+8*i)*ND + n0+tx];
    __syncthreads();
    int ksrc = (tx&~15) | INV16[tx&15];
    #pragma unroll
    for(int i=0;i<4;i++){
        int n = n0 + ty + 8*i;
        Wt[n*KD + k0 + tx] = __float2half_rn(sm[ksrc][ty+8*i]);
    }
}
template<int KD,int ND>
__global__ __launch_bounds__(256)
void wprep_t3(const float* __restrict__ Wa, const float* __restrict__ Wb,
              const float* __restrict__ Wc,
              __half* __restrict__ Ta, __half* __restrict__ Tb, __half* __restrict__ Tc){
    __shared__ float sm[32][33];
    const float* W = (blockIdx.z==0)?Wa:(blockIdx.z==1)?Wb:Wc;
    __half*     T  = (blockIdx.z==0)?Ta:(blockIdx.z==1)?Tb:Tc;
    const int tx = threadIdx.x&31, ty = threadIdx.x>>5;
    const int k0 = blockIdx.x*32, n0 = blockIdx.y*32;
    #pragma unroll
    for(int i=0;i<4;i++)
        sm[ty+8*i][tx] = W[(k0+ty+8*i)*ND + n0+tx];
    __syncthreads();
    int ksrc = (tx&~15) | INV16[tx&15];
    #pragma unroll
    for(int i=0;i<4;i++){
        int n = n0 + ty + 8*i;
        T[n*KD + k0 + tx] = __float2half_rn(sm[ksrc][ty+8*i]);
    }
}

// ---------------- prep: y -> fp16 quad16, 8 elems/thread ----------------
__global__ __launch_bounds__(256)
void yprep8(const float* __restrict__ y, __half* __restrict__ yr){
    int gid = blockIdx.x*256 + threadIdx.x;
    const float* p = y + gid*8;
    float4 v0 = *(const float4*)p;
    float4 v1 = *(const float4*)(p+4);
    // this thread owns logical w = 8*hi + j  (hi = gid&1) of 16-group (gid>>1)
    __half2* d = (__half2*)yr;
    int base = (gid>>1)*8 + (gid&1);   // half2 units
    d[base+0] = __floats2half2_rn(v0.x, v0.y);
    d[base+2] = __floats2half2_rn(v0.z, v0.w);
    d[base+4] = __floats2half2_rn(v1.x, v1.y);
    d[base+6] = __floats2half2_rn(v1.z, v1.w);
}

// ---------------- layernorm: warp per row, fp16 quad16 out ----------------
__global__ __launch_bounds__(256)
void ln_kernel(const float* __restrict__ src, __half* __restrict__ dst,
               const float* __restrict__ gamma, const float* __restrict__ beta)
{
    const int lane = threadIdx.x&31, warp = threadIdx.x>>5;
    const int row = blockIdx.x*8 + warp;
    const float* p = src + row*256 + lane*8;
    float4 v0 = *(const float4*)p;
    float4 v1 = *(const float4*)(p+4);
    float s  = v0.x+v0.y+v0.z+v0.w + v1.x+v1.y+v1.z+v1.w;
    float s2 = v0.x*v0.x+v0.y*v0.y+v0.z*v0.z+v0.w*v0.w
             + v1.x*v1.x+v1.y*v1.y+v1.z*v1.z+v1.w*v1.w;
    #pragma unroll
    for(int o=16;o;o>>=1){
        s  += __shfl_xor_sync(0xffffffffu, s,  o);
        s2 += __shfl_xor_sync(0xffffffffu, s2, o);
    }
    float mu  = s*(1.f/256.f);
    float var = s2*(1.f/256.f) - mu*mu;
    float inv = rsqrtf(var + 1e-5f);
    float4 ga0 = *(const float4*)(gamma + lane*8);
    float4 ga1 = *(const float4*)(gamma + lane*8 + 4);
    float4 be0 = *(const float4*)(beta  + lane*8);
    float4 be1 = *(const float4*)(beta  + lane*8 + 4);
    float t0=(v0.x-mu)*inv*ga0.x+be0.x, t1=(v0.y-mu)*inv*ga0.y+be0.y;
    float t2=(v0.z-mu)*inv*ga0.z+be0.z, t3=(v0.w-mu)*inv*ga0.w+be0.w;
    float t4=(v1.x-mu)*inv*ga1.x+be1.x, t5=(v1.y-mu)*inv*ga1.y+be1.y;
    float t6=(v1.z-mu)*inv*ga1.z+be1.z, t7=(v1.w-mu)*inv*ga1.w+be1.w;
    __half2* d = (__half2*)(dst + row*256);
    int base = (lane>>1)*8 + (lane&1);
    d[base+0] = __floats2half2_rn(t0, t1);
    d[base+2] = __floats2half2_rn(t2, t3);
    d[base+4] = __floats2half2_rn(t4, t5);
    d[base+6] = __floats2half2_rn(t6, t7);
}

// ---------------- fp16 tensor-core GEMM ----------------
// A[M][KDIM] fp16 quad16-k; Wt[NDIM][KDIM] fp16 quad16-k.
// BM=256 (8 warps x m32), BN=64, BK=16, mma m16n8k16.
// MODE 0: Q fp32 [B,H,N,32] | 1: K fp16 attn | 2: V fp16 attn | 3: gelu->H1 fp16 quad16
// MODE 4: resid + acc + bias fp32
template<int KDIM,int NDIM,int MODE>
__global__ __launch_bounds__(256,2)
void gemm_tc(const __half* __restrict__ A, const __half* __restrict__ Wt,
             const float* __restrict__ bias, void* __restrict__ outv,
             const float* __restrict__ resid)
{
    __shared__ __align__(16) __half As[2][256*16];
    __shared__ __align__(16) __half Bs[2][64*16];
    const int tid  = threadIdx.x;
    const int warp = tid>>5, lane = tid&31, g = lane>>2, c = lane&3;
    const int rowBase = blockIdx.y*256;
    const int colBase = blockIdx.x*64;

    float acc[2][8][4];
    #pragma unroll
    for(int mt=0;mt<2;mt++)
        #pragma unroll
        for(int nt=0;nt<8;nt++)
            #pragma unroll
            for(int j=0;j<4;j++) acc[mt][nt][j]=0.f;

    const int NK = KDIM/16;
    // prologue
    #pragma unroll
    for(int i=0;i<2;i++){
        int q = tid + i*256;              // 512 chunks of 16B (8 halves)
        cpa16(&As[0][(q>>1)*16 + (q&1)*8], A + (rowBase + (q>>1))*KDIM + (q&1)*8);
    }
    if(tid < 128)
        cpa16(&Bs[0][(tid>>1)*16 + (tid&1)*8], Wt + (colBase + (tid>>1))*KDIM + (tid&1)*8);
    asm volatile("cp.async.commit_group;");

    #pragma unroll 1
    for(int kt=0; kt<NK; kt++){
        int buf = kt&1;
        __syncthreads();
        if(kt+1 < NK){
            #pragma unroll
            for(int i=0;i<2;i++){
                int q = tid + i*256;
                cpa16(&As[buf^1][(q>>1)*16 + (q&1)*8],
                      A + (rowBase + (q>>1))*KDIM + (kt+1)*16 + (q&1)*8);
            }
            if(tid < 128)
                cpa16(&Bs[buf^1][(tid>>1)*16 + (tid&1)*8],
                      Wt + (colBase + (tid>>1))*KDIM + (kt+1)*16 + (tid&1)*8);
            asm volatile("cp.async.commit_group;");
            asm volatile("cp.async.wait_group 1;");
        } else {
            asm volatile("cp.async.wait_group 0;");
        }
        __syncthreads();

        unsigned af[2][4];
        #pragma unroll
        for(int mt=0;mt<2;mt++){
            int r = warp*32 + mt*16 + g;
            uint2 lo = *(const uint2*)&As[buf][ r   *16 + 4*c];
            uint2 hi = *(const uint2*)&As[buf][(r+8)*16 + 4*c];
            af[mt][0]=lo.x; af[mt][1]=hi.x; af[mt][2]=lo.y; af[mt][3]=hi.y;
        }
        #pragma unroll
        for(int nt=0;nt<8;nt++){
            uint2 bb = *(const uint2*)&Bs[buf][(nt*8+g)*16 + 4*c];
            mmah(acc[0][nt], af[0][0],af[0][1],af[0][2],af[0][3], bb.x,bb.y);
            mmah(acc[1][nt], af[1][0],af[1][1],af[1][2],af[1][3], bb.x,bb.y);
        }
    }

    #pragma unroll
    for(int mt=0;mt<2;mt++)
    #pragma unroll
    for(int i=0;i<2;i++){
        int r = rowBase + warp*32 + mt*16 + g + i*8;
        #pragma unroll
        for(int nt=0;nt<8;nt++){
            int col0 = colBase + nt*8 + 2*c;
            float v0 = acc[mt][nt][i*2+0] + bias[col0];
            float v1 = acc[mt][nt][i*2+1] + bias[col0+1];
            if(MODE==0){
                float* out = (float*)outv;
                int b = r>>11, n = r&2047;
                int h = col0>>5, d = col0&31;
                float2 o; o.x = v0; o.y = v1;
                *(float2*)&out[((b*HH+h)*NN + n)*32 + d] = o;
            } else if(MODE==1){
                __half* oh = (__half*)outv;
                int b = r>>11, n = r&2047;
                int h = col0>>5, d = col0&31;
                int dp = (d&~15) | quad16(d&15);
                *(__half2*)&oh[((b*HH+h)*NN + n)*32 + dp] = __floats2half2_rn(v0, v1);
            } else if(MODE==2){
                __half* oh = (__half*)outv;
                int b = r>>11, n = r&2047;
                int np = (n&~15) | quad16(n&15);
                int h = col0>>5, d = col0&31;
                oh[((b*HH+h)*32 + d  )*NN + np] = __float2half_rn(v0);
                oh[((b*HH+h)*32 + d+1)*NN + np] = __float2half_rn(v1);
            } else if(MODE==3){
                __half* oh = (__half*)outv;
                float g0 = 0.5f*v0*(1.f+erff(v0*0.70710678118654752f));
                float g1 = 0.5f*v1*(1.f+erff(v1*0.70710678118654752f));
                int cp = (col0&~15) | quad16(col0&15);
                *(__half2*)&oh[r*NDIM + cp] = __floats2half2_rn(g0, g1);
            } else {
                float* out = (float*)outv;
                float2 rr = *(const float2*)&resid[r*NDIM + col0];
                float2 o; o.x = rr.x+v0; o.y = rr.y+v1;
                *(float2*)&out[r*NDIM + col0] = o;
            }
        }
    }
}

// ---------------- fp16 tensor-core flash attention + per-head Q residual ----------------
__global__ __launch_bounds__(256,2)
void attn_tc(const float* __restrict__ Q, const __half* __restrict__ K,
             const __half* __restrict__ V, float* __restrict__ O)
{
    __shared__ __align__(16) __half Ks[2][64*48];  // [key][dphys], stride 48 halfs
    __shared__ __align__(16) __half Vs[2][32*80];  // [d][keyphys], stride 80 halfs
    const int tid  = threadIdx.x;
    const int warp = tid>>5, lane = tid&31, g = lane>>2, c = lane&3;
    const int bh = blockIdx.y;
    const int b  = bh>>3, h = bh&7;
    const int qbase = blockIdx.x*128;
    const float*  Qg = Q + (bh*NN + qbase)*32;
    const __half* Kg = K + (long)bh*NN*32;
    const __half* Vg = V + (long)bh*32*NN;

    const float QS = 0.0625f * 1.44269504088896341f;   // log2(e)/16
    unsigned qf[2][4];
    {
        int r0 = warp*16 + g;
        #pragma unroll
        for(int kh=0;kh<2;kh++){
            int d0 = kh*16 + 2*c;
            qf[kh][0] = h2u(Qg[ r0   *32 + d0  ]*QS, Qg[ r0   *32 + d0+1]*QS);
            qf[kh][1] = h2u(Qg[(r0+8)*32 + d0  ]*QS, Qg[(r0+8)*32 + d0+1]*QS);
            qf[kh][2] = h2u(Qg[ r0   *32 + d0+8]*QS, Qg[ r0   *32 + d0+9]*QS);
            qf[kh][3] = h2u(Qg[(r0+8)*32 + d0+8]*QS, Qg[(r0+8)*32 + d0+9]*QS);
        }
    }

    float oacc[4][4];
    #pragma unroll
    for(int nt=0;nt<4;nt++)
        #pragma unroll
        for(int j=0;j<4;j++) oacc[nt][j]=0.f;
    float lacc[4] = {0.f,0.f,0.f,0.f};
    const unsigned ones = (g==0) ? 0x3C003C00u : 0u;   // half2(1,1) at col 0

    cpa16(&Ks[0][(tid>>2)*48 + (tid&3)*8], Kg + (tid>>2)*32 + (tid&3)*8);
    cpa16(&Vs[0][(tid>>3)*80 + (tid&7)*8], Vg + (tid>>3)*NN + (tid&7)*8);
    asm volatile("cp.async.commit_group;");

    #pragma unroll 1
    for(int kt=0; kt<NN/64; kt++){
        int buf = kt&1;
        __syncthreads();
        if(kt+1 < NN/64){
            cpa16(&Ks[buf^1][(tid>>2)*48 + (tid&3)*8],
                  Kg + ((kt+1)*64 + (tid>>2))*32 + (tid&3)*8);
            cpa16(&Vs[buf^1][(tid>>3)*80 + (tid&7)*8],
                  Vg + (tid>>3)*NN + (kt+1)*64 + (tid&7)*8);
            asm volatile("cp.async.commit_group;");
            asm volatile("cp.async.wait_group 1;");
        } else {
            asm volatile("cp.async.wait_group 0;");
        }
        __syncthreads();

        float sv[8][4];
        #pragma unroll
        for(int nt=0;nt<8;nt++)
            #pragma unroll
            for(int j=0;j<4;j++) sv[nt][j]=0.f;
        #pragma unroll
        for(int kh=0;kh<2;kh++){
            #pragma unroll
            for(int nt=0;nt<8;nt++){
                uint2 bb = *(const uint2*)&Ks[buf][(nt*8+g)*48 + kh*16 + 4*c];
                mmah(sv[nt], qf[kh][0],qf[kh][1],qf[kh][2],qf[kh][3], bb.x,bb.y);
            }
        }
        unsigned ph[8][2];
        #pragma unroll
        for(int nt=0;nt<8;nt++){
            ph[nt][0] = ex2h2(h2u(sv[nt][0], sv[nt][1]));
            ph[nt][1] = ex2h2(h2u(sv[nt][2], sv[nt][3]));
        }
        #pragma unroll
        for(int ks=0;ks<4;ks++){
            unsigned a0 = ph[2*ks][0], a1 = ph[2*ks][1];
            unsigned a2 = ph[2*ks+1][0], a3 = ph[2*ks+1][1];
            #pragma unroll
            for(int nt=0;nt<4;nt++){
                uint2 bb = *(const uint2*)&Vs[buf][(nt*8+g)*80 + ks*16 + 4*c];
                mmah(oacc[nt], a0,a1,a2,a3, bb.x,bb.y);
            }
            mmah(lacc, a0,a1,a2,a3, ones, ones);
        }
    }

    float l0 = __shfl_sync(0xffffffffu, lacc[0], lane & ~3);
    float l1 = __shfl_sync(0xffffffffu, lacc[2], lane & ~3);
    float inv0 = 1.f/l0, inv1 = 1.f/l1;

    #pragma unroll
    for(int i=0;i<2;i++){
        int rloc = warp*16 + g + i*8;
        int row  = qbase + rloc;
        float inv = (i==0) ? inv0 : inv1;
        #pragma unroll
        for(int nt=0;nt<4;nt++){
            int col = nt*8 + 2*c;
            float q0 = Qg[rloc*32 + col];
            float q1 = Qg[rloc*32 + col + 1];
            float2 o;
            o.x = q0 + oacc[nt][i*2+0]*inv;
            o.y = q1 + oacc[nt][i*2+1]*inv;
            *(float2*)&O[((long)b*NN + row)*DV + h*32 + col] = o;
        }
    }
}

// ---------------- launch ----------------
extern "C" void kernel_launch(void* const* d_in, const int* /*in_sizes*/, int /*n_in*/,
                              void* d_out, int /*out_size*/)
{
    const float* x     = (const float*)d_in[0];
    const float* y     = (const float*)d_in[1];
    const float* Wq    = (const float*)d_in[2];
    const float* bq    = (const float*)d_in[3];
    const float* Wk    = (const float*)d_in[4];
    const float* bk    = (const float*)d_in[5];
    const float* Wv    = (const float*)d_in[6];
    const float* bv    = (const float*)d_in[7];
    const float* W1    = (const float*)d_in[8];
    const float* b1    = (const float*)d_in[9];
    const float* W2    = (const float*)d_in[10];
    const float* b2    = (const float*)d_in[11];
    const float* ln0_g = (const float*)d_in[12];
    const float* ln0_b = (const float*)d_in[13];
    const float* ln1_g = (const float*)d_in[14];
    const float* ln1_b = (const float*)d_in[15];
    float* out = (float*)d_out;

    float *Q,*O;
    __half *xn,*yr,*K,*V,*On,*H1,*wq,*wk,*wv,*w1,*w2;
    cudaGetSymbolAddress((void**)&xn, g_xn);
    cudaGetSymbolAddress((void**)&yr, g_yr);
    cudaGetSymbolAddress((void**)&Q,  g_Q);
    cudaGetSymbolAddress((void**)&K,  g_K);
    cudaGetSymbolAddress((void**)&V,  g_V);
    cudaGetSymbolAddress((void**)&O,  g_O);
    cudaGetSymbolAddress((void**)&On, g_On);
    cudaGetSymbolAddress((void**)&H1, g_H1);
    cudaGetSymbolAddress((void**)&wq, g_Wq);
    cudaGetSymbolAddress((void**)&wk, g_Wk);
    cudaGetSymbolAddress((void**)&wv, g_Wv);
    cudaGetSymbolAddress((void**)&w1, g_W1);
    cudaGetSymbolAddress((void**)&w2, g_W2);

    wprep_t3<DV,DV><<<dim3(8,8,3), 256>>>(Wq, Wk, Wv, wq, wk, wv);
    wprep_t<DV,DFF><<<dim3(8,16), 256>>>(W1, w1);
    wprep_t<DFF,DV><<<dim3(16,8), 256>>>(W2, w2);
    yprep8<<<MROWS*DV/2048, 256>>>(y, yr);

    ln_kernel<<<MROWS/8, 256>>>(x, xn, ln0_g, ln0_b);
    gemm_tc<256,256,0><<<dim3(4, 64), 256>>>(xn, wq, bq, Q,  nullptr);
    gemm_tc<256,256,1><<<dim3(4, 64), 256>>>(yr, wk, bk, K,  nullptr);
    gemm_tc<256,256,2><<<dim3(4, 64), 256>>>(yr, wv, bv, V,  nullptr);
    attn_tc<<<dim3(NN/128, BB*HH), 256>>>(Q, K, V, O);
    ln_kernel<<<MROWS/8, 256>>>(O, On, ln1_g, ln1_b);
    gemm_tc<256,512,3><<<dim3(8, 64), 256>>>(On, w1, b1, H1, nullptr);
    gemm_tc<512,256,4><<<dim3(4, 64), 256>>>(H1, w2, b2, out, O);
}

// round 12
// speedup vs baseline: 7.0151x; 1.1157x over previous
#include <cuda_runtime.h>
#include <cuda_fp16.h>
#include <math.h>

#define BB 8
#define NN 2048
#define DV 256
#define HH 8
#define DFF 512
#define MROWS (BB*NN)

// ---------------- scratch ----------------
__device__ __half g_xn[MROWS*DV];    // ln0 out, fp16, k quad16-interleaved
__device__ __half g_yr[MROWS*DV];    // y fp16, k quad16
__device__ float  g_Q [MROWS*DV];    // [B,H,N,32] fp32 exact
__device__ __half g_K [MROWS*DV];    // [B,H,N,32] d quad16, fp16
__device__ __half g_V [MROWS*DV];    // [B,H,32,N] key quad16, fp16
__device__ float  g_O [MROWS*DV];    // exact
__device__ __half g_On[MROWS*DV];    // ln1 out fp16 quad16
__device__ __half g_H1[MROWS*DFF];   // gelu out fp16 quad16
__device__ __half g_Wq[DV*DV];       // Wt[n][kphys] fp16
__device__ __half g_Wk[DV*DV];
__device__ __half g_Wv[DV*DV];
__device__ __half g_W1[DV*DFF];
__device__ __half g_W2[DFF*DV];

__device__ __forceinline__ unsigned h2u(float lo, float hi){
    unsigned r; asm("cvt.rn.f16x2.f32 %0, %1, %2;" : "=r"(r) : "f"(hi), "f"(lo)); return r;
}
__device__ __forceinline__ unsigned ex2h2(unsigned x){
    unsigned r; asm("ex2.approx.f16x2 %0, %1;" : "=r"(r) : "r"(x)); return r;
}
__device__ __forceinline__ void mmah(float* c, unsigned a0,unsigned a1,unsigned a2,unsigned a3,
                                     unsigned b0,unsigned b1){
    asm volatile("mma.sync.aligned.m16n8k16.row.col.f32.f16.f16.f32 "
      "{%0,%1,%2,%3}, {%4,%5,%6,%7}, {%8,%9}, {%0,%1,%2,%3};"
      : "+f"(c[0]),"+f"(c[1]),"+f"(c[2]),"+f"(c[3])
      : "r"(a0),"r"(a1),"r"(a2),"r"(a3),"r"(b0),"r"(b1));
}
// quad-interleave within 16-group: w=8*hi+2*cc+lo -> 4*cc+2*hi+lo
__device__ __forceinline__ int quad16(int w){
    return ((w&7)>>1)*4 + ((w>>3)&1)*2 + (w&1);
}
// inverse: phys p -> logical w
__device__ __forceinline__ int iquad16(int p){
    return (((p>>1)&1)<<3) | (((p>>2)&3)<<1) | (p&1);
}
__device__ __forceinline__ void cpa16(void* smem, const void* gmem){
    unsigned s = (unsigned)__cvta_generic_to_shared(smem);
    asm volatile("cp.async.cg.shared.global [%0], [%1], 16;" :: "r"(s), "l"(gmem));
}

// ---------------- device bodies for fused prep ----------------
// transpose one 32x32 tile of W[k][n] -> Wt[n][kphys] fp16 (k quad16)
__device__ __forceinline__ void wtile_body(const float* __restrict__ W, __half* __restrict__ T,
                                           int KD, int ND, int k0, int n0,
                                           int tx, int ty, float (*sm)[33]){
    #pragma unroll
    for(int i=0;i<4;i++)
        sm[ty+8*i][tx] = W[(k0+ty+8*i)*ND + n0+tx];
    __syncthreads();
    int ksrc = (tx&~15) | iquad16(tx&15);
    #pragma unroll
    for(int i=0;i<4;i++){
        int n = n0 + ty + 8*i;
        T[n*KD + k0 + tx] = __float2half_rn(sm[ksrc][ty+8*i]);
    }
}
// y -> fp16 quad16; one 16-float group per thread, coalesced uint4 stores
__device__ __forceinline__ void yprep_body(const float* __restrict__ y, __half* __restrict__ yr,
                                           int gid){
    const float4* p = (const float4*)(y + gid*16);
    float4 a = p[0], b = p[1], c2 = p[2], d = p[3];   // w0-3, w4-7, w8-11, w12-15
    uint4 o0, o1;
    o0.x = h2u(a.x,a.y);   o0.y = h2u(c2.x,c2.y);
    o0.z = h2u(a.z,a.w);   o0.w = h2u(c2.z,c2.w);
    o1.x = h2u(b.x,b.y);   o1.y = h2u(d.x,d.y);
    o1.z = h2u(b.z,b.w);   o1.w = h2u(d.z,d.w);
    ((uint4*)yr)[gid*2]   = o0;
    ((uint4*)yr)[gid*2+1] = o1;
}
// layernorm row (warp-collective), fp16 quad16 out, lane-paired uint4 stores
__device__ __forceinline__ void ln_body(const float* __restrict__ src, __half* __restrict__ dst,
                                        const float* __restrict__ gamma,
                                        const float* __restrict__ beta,
                                        int row, int lane){
    const float* p = src + row*256 + lane*8;
    float4 v0 = *(const float4*)p;
    float4 v1 = *(const float4*)(p+4);
    float s  = v0.x+v0.y+v0.z+v0.w + v1.x+v1.y+v1.z+v1.w;
    float s2 = v0.x*v0.x+v0.y*v0.y+v0.z*v0.z+v0.w*v0.w
             + v1.x*v1.x+v1.y*v1.y+v1.z*v1.z+v1.w*v1.w;
    #pragma unroll
    for(int o=16;o;o>>=1){
        s  += __shfl_xor_sync(0xffffffffu, s,  o);
        s2 += __shfl_xor_sync(0xffffffffu, s2, o);
    }
    float mu  = s*(1.f/256.f);
    float var = s2*(1.f/256.f) - mu*mu;
    float inv = rsqrtf(var + 1e-5f);
    float4 ga0 = *(const float4*)(gamma + lane*8);
    float4 ga1 = *(const float4*)(gamma + lane*8 + 4);
    float4 be0 = *(const float4*)(beta  + lane*8);
    float4 be1 = *(const float4*)(beta  + lane*8 + 4);
    float t0=(v0.x-mu)*inv*ga0.x+be0.x, t1=(v0.y-mu)*inv*ga0.y+be0.y;
    float t2=(v0.z-mu)*inv*ga0.z+be0.z, t3=(v0.w-mu)*inv*ga0.w+be0.w;
    float t4=(v1.x-mu)*inv*ga1.x+be1.x, t5=(v1.y-mu)*inv*ga1.y+be1.y;
    float t6=(v1.z-mu)*inv*ga1.z+be1.z, t7=(v1.w-mu)*inv*ga1.w+be1.w;
    unsigned h0 = h2u(t0,t1), h1 = h2u(t2,t3), h2_ = h2u(t4,t5), h3 = h2u(t6,t7);
    unsigned x0 = __shfl_xor_sync(0xffffffffu, h0, 1);
    unsigned x1 = __shfl_xor_sync(0xffffffffu, h1, 1);
    unsigned x2 = __shfl_xor_sync(0xffffffffu, h2_, 1);
    unsigned x3 = __shfl_xor_sync(0xffffffffu, h3, 1);
    uint4* base = (uint4*)(dst + row*256 + (lane>>1)*16);
    if(lane & 1) base[1] = make_uint4(x2, h2_, x3, h3);
    else         base[0] = make_uint4(h0, x0, h1, x1);
}

// ---------------- fused prep: weight transposes + yprep + ln0, one launch ----------------
#define PB_W3 192
#define PB_W1 (PB_W3+128)
#define PB_W2 (PB_W1+128)
#define PB_Y  (PB_W2+1024)
#define PB_LN (PB_Y+2048)
__global__ __launch_bounds__(256)
void prep_all(const float* __restrict__ Wq, const float* __restrict__ Wk,
              const float* __restrict__ Wv, const float* __restrict__ W1,
              const float* __restrict__ W2, const float* __restrict__ y,
              const float* __restrict__ x,
              const float* __restrict__ ln0_g, const float* __restrict__ ln0_b,
              __half* __restrict__ wq, __half* __restrict__ wk, __half* __restrict__ wv,
              __half* __restrict__ w1, __half* __restrict__ w2,
              __half* __restrict__ yr, __half* __restrict__ xn)
{
    __shared__ float sm[32][33];
    const int blk = blockIdx.x;
    const int tid = threadIdx.x;
    const int tx = tid&31, ty = tid>>5;
    if(blk < PB_W3){
        int w = blk/64, rem = blk%64;
        const float* W = (w==0)?Wq:(w==1)?Wk:Wv;
        __half*     T  = (w==0)?wq:(w==1)?wk:wv;
        wtile_body(W, T, DV, DV, (rem%8)*32, (rem/8)*32, tx, ty, sm);
    } else if(blk < PB_W1){
        int rem = blk - PB_W3;
        wtile_body(W1, w1, DV, DFF, (rem%8)*32, (rem/8)*32, tx, ty, sm);
    } else if(blk < PB_W2){
        int rem = blk - PB_W1;
        wtile_body(W2, w2, DFF, DV, (rem%16)*32, (rem/16)*32, tx, ty, sm);
    } else if(blk < PB_Y){
        int gid = (blk - PB_W2)*256 + tid;
        yprep_body(y, yr, gid);
    } else {
        int row = (blk - PB_Y)*8 + ty;
        ln_body(x, xn, ln0_g, ln0_b, row, tx);
    }
}

// ---------------- standalone layernorm (ln1) ----------------
__global__ __launch_bounds__(256)
void ln_kernel(const float* __restrict__ src, __half* __restrict__ dst,
               const float* __restrict__ gamma, const float* __restrict__ beta)
{
    ln_body(src, dst, gamma, beta, blockIdx.x*8 + (threadIdx.x>>5), threadIdx.x&31);
}

// ---------------- fp16 GEMM: 3-stage cp.async, BK=32, one barrier/iter ----------------
// A[M][KDIM] fp16 quad16-k; Wt[NDIM][KDIM] fp16 quad16-k. BM=256, BN=64.
// stage row stride 48 halves (24 words) -> conflict-free frag LDS.
// MODE 0: Q fp32 | 1: K attn fp16 | 2: V attn fp16 | 3: gelu->H1 fp16 quad16 | 4: resid out
#define ASTG (256*48)
#define BSTG (64*48)
#define SMEM_GEMM ((3*ASTG + 3*BSTG)*2)
template<int KDIM,int NDIM,int MODE>
__global__ __launch_bounds__(256,2)
void gemm_tc(const __half* __restrict__ A, const __half* __restrict__ Wt,
             const float* __restrict__ bias, void* __restrict__ outv,
             const float* __restrict__ resid)
{
    extern __shared__ __half dyn[];
    __half* As = dyn;
    __half* Bs = dyn + 3*ASTG;
    const int tid  = threadIdx.x;
    const int warp = tid>>5, lane = tid&31, g = lane>>2, c = lane&3;
    const int rowBase = blockIdx.y*256;
    const int colBase = blockIdx.x*64;

    float acc[2][8][4];
    #pragma unroll
    for(int mt=0;mt<2;mt++)
        #pragma unroll
        for(int nt=0;nt<8;nt++)
            #pragma unroll
            for(int j=0;j<4;j++) acc[mt][nt][j]=0.f;

    const int NK = KDIM/32;
    const int ar = tid>>2, ap = tid&3;     // A chunk base: 4 chunks/thread
    const int br = tid>>2, bp = tid&3;     // B: 256 chunks = 1/thread

    // prologue: stages 0,1
    #pragma unroll
    for(int st=0; st<2; st++){
        #pragma unroll
        for(int i=0;i<4;i++){
            int row = ar + i*64;
            cpa16(&As[st*ASTG + row*48 + ap*8], A + (rowBase+row)*KDIM + st*32 + ap*8);
        }
        cpa16(&Bs[st*BSTG + br*48 + bp*8], Wt + (colBase+br)*KDIM + st*32 + bp*8);
        asm volatile("cp.async.commit_group;");
    }

    #pragma unroll 1
    for(int kt=0; kt<NK; kt++){
        const int cur = kt%3;
        asm volatile("cp.async.wait_group 1;");
        __syncthreads();
        if(kt+2 < NK){
            const int nx = (kt+2)%3;
            #pragma unroll
            for(int i=0;i<4;i++){
                int row = ar + i*64;
                cpa16(&As[nx*ASTG + row*48 + ap*8],
                      A + (rowBase+row)*KDIM + (kt+2)*32 + ap*8);
            }
            cpa16(&Bs[nx*BSTG + br*48 + bp*8],
                  Wt + (colBase+br)*KDIM + (kt+2)*32 + bp*8);
        }
        asm volatile("cp.async.commit_group;");

        #pragma unroll
        for(int ks=0;ks<2;ks++){
            unsigned af[2][4];
            #pragma unroll
            for(int mt=0;mt<2;mt++){
                int r = warp*32 + mt*16 + g;
                uint2 lo = *(const uint2*)&As[cur*ASTG +  r   *48 + ks*16 + 4*c];
                uint2 hi = *(const uint2*)&As[cur*ASTG + (r+8)*48 + ks*16 + 4*c];
                af[mt][0]=lo.x; af[mt][1]=hi.x; af[mt][2]=lo.y; af[mt][3]=hi.y;
            }
            #pragma unroll
            for(int nt=0;nt<8;nt++){
                uint2 bb = *(const uint2*)&Bs[cur*BSTG + (nt*8+g)*48 + ks*16 + 4*c];
                mmah(acc[0][nt], af[0][0],af[0][1],af[0][2],af[0][3], bb.x,bb.y);
                mmah(acc[1][nt], af[1][0],af[1][1],af[1][2],af[1][3], bb.x,bb.y);
            }
        }
    }

    #pragma unroll
    for(int mt=0;mt<2;mt++)
    #pragma unroll
    for(int i=0;i<2;i++){
        int r = rowBase + warp*32 + mt*16 + g + i*8;
        #pragma unroll
        for(int nt=0;nt<8;nt++){
            int col0 = colBase + nt*8 + 2*c;
            float v0 = acc[mt][nt][i*2+0] + bias[col0];
            float v1 = acc[mt][nt][i*2+1] + bias[col0+1];
            if(MODE==0){
                float* out = (float*)outv;
                int b = r>>11, n = r&2047;
                int h = col0>>5, d = col0&31;
                float2 o; o.x = v0; o.y = v1;
                *(float2*)&out[((b*HH+h)*NN + n)*32 + d] = o;
            } else if(MODE==1){
                __half* oh = (__half*)outv;
                int b = r>>11, n = r&2047;
                int h = col0>>5, d = col0&31;
                int dp = (d&~15) | quad16(d&15);
                *(__half2*)&oh[((b*HH+h)*NN + n)*32 + dp] = __floats2half2_rn(v0, v1);
            } else if(MODE==2){
                __half* oh = (__half*)outv;
                int b = r>>11, n = r&2047;
                int np = (n&~15) | quad16(n&15);
                int h = col0>>5, d = col0&31;
                oh[((b*HH+h)*32 + d  )*NN + np] = __float2half_rn(v0);
                oh[((b*HH+h)*32 + d+1)*NN + np] = __float2half_rn(v1);
            } else if(MODE==3){
                __half* oh = (__half*)outv;
                float g0 = 0.5f*v0*(1.f+erff(v0*0.70710678118654752f));
                float g1 = 0.5f*v1*(1.f+erff(v1*0.70710678118654752f));
                int cp = (col0&~15) | quad16(col0&15);
                *(__half2*)&oh[r*NDIM + cp] = __floats2half2_rn(g0, g1);
            } else {
                float* out = (float*)outv;
                float2 rr = *(const float2*)&resid[r*NDIM + col0];
                float2 o; o.x = rr.x+v0; o.y = rr.y+v1;
                *(float2*)&out[r*NDIM + col0] = o;
            }
        }
    }
}

// ---------------- fp16 tensor-core flash attention + per-head Q residual ----------------
__global__ __launch_bounds__(256,2)
void attn_tc(const float* __restrict__ Q, const __half* __restrict__ K,
             const __half* __restrict__ V, float* __restrict__ O)
{
    __shared__ __align__(16) __half Ks[2][64*48];
    __shared__ __align__(16) __half Vs[2][32*80];
    const int tid  = threadIdx.x;
    const int warp = tid>>5, lane = tid&31, g = lane>>2, c = lane&3;
    const int bh = blockIdx.y;
    const int b  = bh>>3, h = bh&7;
    const int qbase = blockIdx.x*128;
    const float*  Qg = Q + (bh*NN + qbase)*32;
    const __half* Kg = K + (long)bh*NN*32;
    const __half* Vg = V + (long)bh*32*NN;

    const float QS = 0.0625f * 1.44269504088896341f;
    unsigned qf[2][4];
    {
        int r0 = warp*16 + g;
        #pragma unroll
        for(int kh=0;kh<2;kh++){
            int d0 = kh*16 + 2*c;
            qf[kh][0] = h2u(Qg[ r0   *32 + d0  ]*QS, Qg[ r0   *32 + d0+1]*QS);
            qf[kh][1] = h2u(Qg[(r0+8)*32 + d0  ]*QS, Qg[(r0+8)*32 + d0+1]*QS);
            qf[kh][2] = h2u(Qg[ r0   *32 + d0+8]*QS, Qg[ r0   *32 + d0+9]*QS);
            qf[kh][3] = h2u(Qg[(r0+8)*32 + d0+8]*QS, Qg[(r0+8)*32 + d0+9]*QS);
        }
    }

    float oacc[4][4];
    #pragma unroll
    for(int nt=0;nt<4;nt++)
        #pragma unroll
        for(int j=0;j<4;j++) oacc[nt][j]=0.f;
    float lacc[4] = {0.f,0.f,0.f,0.f};
    const unsigned ones = (g==0) ? 0x3C003C00u : 0u;

    cpa16(&Ks[0][(tid>>2)*48 + (tid&3)*8], Kg + (tid>>2)*32 + (tid&3)*8);
    cpa16(&Vs[0][(tid>>3)*80 + (tid&7)*8], Vg + (tid>>3)*NN + (tid&7)*8);
    asm volatile("cp.async.commit_group;");

    #pragma unroll 1
    for(int kt=0; kt<NN/64; kt++){
        int buf = kt&1;
        __syncthreads();
        if(kt+1 < NN/64){
            cpa16(&Ks[buf^1][(tid>>2)*48 + (tid&3)*8],
                  Kg + ((kt+1)*64 + (tid>>2))*32 + (tid&3)*8);
            cpa16(&Vs[buf^1][(tid>>3)*80 + (tid&7)*8],
                  Vg + (tid>>3)*NN + (kt+1)*64 + (tid&7)*8);
            asm volatile("cp.async.commit_group;");
            asm volatile("cp.async.wait_group 1;");
        } else {
            asm volatile("cp.async.wait_group 0;");
        }
        __syncthreads();

        float sv[8][4];
        #pragma unroll
        for(int nt=0;nt<8;nt++)
            #pragma unroll
            for(int j=0;j<4;j++) sv[nt][j]=0.f;
        #pragma unroll
        for(int kh=0;kh<2;kh++){
            #pragma unroll
            for(int nt=0;nt<8;nt++){
                uint2 bb = *(const uint2*)&Ks[buf][(nt*8+g)*48 + kh*16 + 4*c];
                mmah(sv[nt], qf[kh][0],qf[kh][1],qf[kh][2],qf[kh][3], bb.x,bb.y);
            }
        }
        unsigned ph[8][2];
        #pragma unroll
        for(int nt=0;nt<8;nt++){
            ph[nt][0] = ex2h2(h2u(sv[nt][0], sv[nt][1]));
            ph[nt][1] = ex2h2(h2u(sv[nt][2], sv[nt][3]));
        }
        #pragma unroll
        for(int ks=0;ks<4;ks++){
            unsigned a0 = ph[2*ks][0], a1 = ph[2*ks][1];
            unsigned a2 = ph[2*ks+1][0], a3 = ph[2*ks+1][1];
            #pragma unroll
            for(int nt=0;nt<4;nt++){
                uint2 bb = *(const uint2*)&Vs[buf][(nt*8+g)*80 + ks*16 + 4*c];
                mmah(oacc[nt], a0,a1,a2,a3, bb.x,bb.y);
            }
            mmah(lacc, a0,a1,a2,a3, ones, ones);
        }
    }

    float l0 = __shfl_sync(0xffffffffu, lacc[0], lane & ~3);
    float l1 = __shfl_sync(0xffffffffu, lacc[2], lane & ~3);
    float inv0 = 1.f/l0, inv1 = 1.f/l1;

    #pragma unroll
    for(int i=0;i<2;i++){
        int rloc = warp*16 + g + i*8;
        int row  = qbase + rloc;
        float inv = (i==0) ? inv0 : inv1;
        #pragma unroll
        for(int nt=0;nt<4;nt++){
            int col = nt*8 + 2*c;
            float q0 = Qg[rloc*32 + col];
            float q1 = Qg[rloc*32 + col + 1];
            float2 o;
            o.x = q0 + oacc[nt][i*2+0]*inv;
            o.y = q1 + oacc[nt][i*2+1]*inv;
            *(float2*)&O[((long)b*NN + row)*DV + h*32 + col] = o;
        }
    }
}

// ---------------- launch ----------------
extern "C" void kernel_launch(void* const* d_in, const int* /*in_sizes*/, int /*n_in*/,
                              void* d_out, int /*out_size*/)
{
    const float* x     = (const float*)d_in[0];
    const float* y     = (const float*)d_in[1];
    const float* Wq    = (const float*)d_in[2];
    const float* bq    = (const float*)d_in[3];
    const float* Wk    = (const float*)d_in[4];
    const float* bk    = (const float*)d_in[5];
    const float* Wv    = (const float*)d_in[6];
    const float* bv    = (const float*)d_in[7];
    const float* W1    = (const float*)d_in[8];
    const float* b1    = (const float*)d_in[9];
    const float* W2    = (const float*)d_in[10];
    const float* b2    = (const float*)d_in[11];
    const float* ln0_g = (const float*)d_in[12];
    const float* ln0_b = (const float*)d_in[13];
    const float* ln1_g = (const float*)d_in[14];
    const float* ln1_b = (const float*)d_in[15];
    float* out = (float*)d_out;

    float *Q,*O;
    __half *xn,*yr,*K,*V,*On,*H1,*wq,*wk,*wv,*w1,*w2;
    cudaGetSymbolAddress((void**)&xn, g_xn);
    cudaGetSymbolAddress((void**)&yr, g_yr);
    cudaGetSymbolAddress((void**)&Q,  g_Q);
    cudaGetSymbolAddress((void**)&K,  g_K);
    cudaGetSymbolAddress((void**)&V,  g_V);
    cudaGetSymbolAddress((void**)&O,  g_O);
    cudaGetSymbolAddress((void**)&On, g_On);
    cudaGetSymbolAddress((void**)&H1, g_H1);
    cudaGetSymbolAddress((void**)&wq, g_Wq);
    cudaGetSymbolAddress((void**)&wk, g_Wk);
    cudaGetSymbolAddress((void**)&wv, g_Wv);
    cudaGetSymbolAddress((void**)&w1, g_W1);
    cudaGetSymbolAddress((void**)&w2, g_W2);

    cudaFuncSetAttribute(gemm_tc<256,256,0>, cudaFuncAttributeMaxDynamicSharedMemorySize, SMEM_GEMM);
    cudaFuncSetAttribute(gemm_tc<256,256,1>, cudaFuncAttributeMaxDynamicSharedMemorySize, SMEM_GEMM);
    cudaFuncSetAttribute(gemm_tc<256,256,2>, cudaFuncAttributeMaxDynamicSharedMemorySize, SMEM_GEMM);
    cudaFuncSetAttribute(gemm_tc<256,512,3>, cudaFuncAttributeMaxDynamicSharedMemorySize, SMEM_GEMM);
    cudaFuncSetAttribute(gemm_tc<512,256,4>, cudaFuncAttributeMaxDynamicSharedMemorySize, SMEM_GEMM);

    prep_all<<<PB_LN, 256>>>(Wq, Wk, Wv, W1, W2, y, x, ln0_g, ln0_b,
                             wq, wk, wv, w1, w2, yr, xn);
    gemm_tc<256,256,0><<<dim3(4, 64), 256, SMEM_GEMM>>>(xn, wq, bq, Q,  nullptr);
    gemm_tc<256,256,1><<<dim3(4, 64), 256, SMEM_GEMM>>>(yr, wk, bk, K,  nullptr);
    gemm_tc<256,256,2><<<dim3(4, 64), 256, SMEM_GEMM>>>(yr, wv, bv, V,  nullptr);
    attn_tc<<<dim3(NN/128, BB*HH), 256>>>(Q, K, V, O);
    ln_kernel<<<MROWS/8, 256>>>(O, On, ln1_g, ln1_b);
    gemm_tc<256,512,3><<<dim3(8, 64), 256, SMEM_GEMM>>>(On, w1, b1, H1, nullptr);
    gemm_tc<512,256,4><<<dim3(4, 64), 256, SMEM_GEMM>>>(H1, w2, b2, out, O);
}

// round 13
// speedup vs baseline: 7.0746x; 1.0085x over previous
#include <cuda_runtime.h>
#include <cuda_fp16.h>
#include <math.h>

#define BB 8
#define NN 2048
#define DV 256
#define HH 8
#define DFF 512
#define MROWS (BB*NN)

// ---------------- scratch ----------------
__device__ __half g_xn[MROWS*DV];    // ln0 out, fp16, k quad16-interleaved
__device__ __half g_yr[MROWS*DV];    // y fp16, k quad16
__device__ float  g_Q [MROWS*DV];    // [B,H,N,32] fp32 exact
__device__ __half g_K [MROWS*DV];    // [B,H,N,32] d quad16, fp16
__device__ __half g_V [MROWS*DV];    // [B,H,32,N] key quad16, fp16
__device__ float  g_O [MROWS*DV];    // exact
__device__ __half g_On[MROWS*DV];    // ln1 out fp16 quad16
__device__ __half g_H1[MROWS*DFF];   // gelu out fp16 quad16
__device__ __half g_Wq[DV*DV];       // Wt[n][kphys] fp16
__device__ __half g_Wk[DV*DV];
__device__ __half g_Wv[DV*DV];
__device__ __half g_W1[DV*DFF];
__device__ __half g_W2[DFF*DV];

__device__ __forceinline__ unsigned h2u(float lo, float hi){
    unsigned r; asm("cvt.rn.f16x2.f32 %0, %1, %2;" : "=r"(r) : "f"(hi), "f"(lo)); return r;
}
__device__ __forceinline__ unsigned ex2h2(unsigned x){
    unsigned r; asm("ex2.approx.f16x2 %0, %1;" : "=r"(r) : "r"(x)); return r;
}
__device__ __forceinline__ void mmah(float* c, unsigned a0,unsigned a1,unsigned a2,unsigned a3,
                                     unsigned b0,unsigned b1){
    asm volatile("mma.sync.aligned.m16n8k16.row.col.f32.f16.f16.f32 "
      "{%0,%1,%2,%3}, {%4,%5,%6,%7}, {%8,%9}, {%0,%1,%2,%3};"
      : "+f"(c[0]),"+f"(c[1]),"+f"(c[2]),"+f"(c[3])
      : "r"(a0),"r"(a1),"r"(a2),"r"(a3),"r"(b0),"r"(b1));
}
// quad-interleave within 16-group: w=8*hi+2*cc+lo -> 4*cc+2*hi+lo
__device__ __forceinline__ int quad16(int w){
    return ((w&7)>>1)*4 + ((w>>3)&1)*2 + (w&1);
}
// inverse: phys p -> logical w
__device__ __forceinline__ int iquad16(int p){
    return (((p>>1)&1)<<3) | (((p>>2)&3)<<1) | (p&1);
}
__device__ __forceinline__ void cpa16(void* smem, const void* gmem){
    unsigned s = (unsigned)__cvta_generic_to_shared(smem);
    asm volatile("cp.async.cg.shared.global [%0], [%1], 16;" :: "r"(s), "l"(gmem));
}
__device__ __forceinline__ float gelu1(float v){
    return 0.5f*v*(1.f+erff(v*0.70710678118654752f));
}

// ---------------- fused prep bodies ----------------
__device__ __forceinline__ void wtile_body(const float* __restrict__ W, __half* __restrict__ T,
                                           int KD, int ND, int k0, int n0,
                                           int tx, int ty, float (*sm)[33]){
    #pragma unroll
    for(int i=0;i<4;i++)
        sm[ty+8*i][tx] = W[(k0+ty+8*i)*ND + n0+tx];
    __syncthreads();
    int ksrc = (tx&~15) | iquad16(tx&15);
    #pragma unroll
    for(int i=0;i<4;i++){
        int n = n0 + ty + 8*i;
        T[n*KD + k0 + tx] = __float2half_rn(sm[ksrc][ty+8*i]);
    }
}
__device__ __forceinline__ void yprep_body(const float* __restrict__ y, __half* __restrict__ yr,
                                           int gid){
    const float4* p = (const float4*)(y + gid*16);
    float4 a = p[0], b = p[1], c2 = p[2], d = p[3];
    uint4 o0, o1;
    o0.x = h2u(a.x,a.y);   o0.y = h2u(c2.x,c2.y);
    o0.z = h2u(a.z,a.w);   o0.w = h2u(c2.z,c2.w);
    o1.x = h2u(b.x,b.y);   o1.y = h2u(d.x,d.y);
    o1.z = h2u(b.z,b.w);   o1.w = h2u(d.z,d.w);
    ((uint4*)yr)[gid*2]   = o0;
    ((uint4*)yr)[gid*2+1] = o1;
}
__device__ __forceinline__ void ln_body(const float* __restrict__ src, __half* __restrict__ dst,
                                        const float* __restrict__ gamma,
                                        const float* __restrict__ beta,
                                        int row, int lane){
    const float* p = src + row*256 + lane*8;
    float4 v0 = *(const float4*)p;
    float4 v1 = *(const float4*)(p+4);
    float s  = v0.x+v0.y+v0.z+v0.w + v1.x+v1.y+v1.z+v1.w;
    float s2 = v0.x*v0.x+v0.y*v0.y+v0.z*v0.z+v0.w*v0.w
             + v1.x*v1.x+v1.y*v1.y+v1.z*v1.z+v1.w*v1.w;
    #pragma unroll
    for(int o=16;o;o>>=1){
        s  += __shfl_xor_sync(0xffffffffu, s,  o);
        s2 += __shfl_xor_sync(0xffffffffu, s2, o);
    }
    float mu  = s*(1.f/256.f);
    float var = s2*(1.f/256.f) - mu*mu;
    float inv = rsqrtf(var + 1e-5f);
    float4 ga0 = *(const float4*)(gamma + lane*8);
    float4 ga1 = *(const float4*)(gamma + lane*8 + 4);
    float4 be0 = *(const float4*)(beta  + lane*8);
    float4 be1 = *(const float4*)(beta  + lane*8 + 4);
    float t0=(v0.x-mu)*inv*ga0.x+be0.x, t1=(v0.y-mu)*inv*ga0.y+be0.y;
    float t2=(v0.z-mu)*inv*ga0.z+be0.z, t3=(v0.w-mu)*inv*ga0.w+be0.w;
    float t4=(v1.x-mu)*inv*ga1.x+be1.x, t5=(v1.y-mu)*inv*ga1.y+be1.y;
    float t6=(v1.z-mu)*inv*ga1.z+be1.z, t7=(v1.w-mu)*inv*ga1.w+be1.w;
    unsigned h0 = h2u(t0,t1), h1 = h2u(t2,t3), h2_ = h2u(t4,t5), h3 = h2u(t6,t7);
    unsigned x0 = __shfl_xor_sync(0xffffffffu, h0, 1);
    unsigned x1 = __shfl_xor_sync(0xffffffffu, h1, 1);
    unsigned x2 = __shfl_xor_sync(0xffffffffu, h2_, 1);
    unsigned x3 = __shfl_xor_sync(0xffffffffu, h3, 1);
    uint4* base = (uint4*)(dst + row*256 + (lane>>1)*16);
    if(lane & 1) base[1] = make_uint4(x2, h2_, x3, h3);
    else         base[0] = make_uint4(h0, x0, h1, x1);
}

#define PB_W3 192
#define PB_W1 (PB_W3+128)
#define PB_W2 (PB_W1+128)
#define PB_Y  (PB_W2+1024)
#define PB_LN (PB_Y+2048)
__global__ __launch_bounds__(256)
void prep_all(const float* __restrict__ Wq, const float* __restrict__ Wk,
              const float* __restrict__ Wv, const float* __restrict__ W1,
              const float* __restrict__ W2, const float* __restrict__ y,
              const float* __restrict__ x,
              const float* __restrict__ ln0_g, const float* __restrict__ ln0_b,
              __half* __restrict__ wq, __half* __restrict__ wk, __half* __restrict__ wv,
              __half* __restrict__ w1, __half* __restrict__ w2,
              __half* __restrict__ yr, __half* __restrict__ xn)
{
    __shared__ float sm[32][33];
    const int blk = blockIdx.x;
    const int tid = threadIdx.x;
    const int tx = tid&31, ty = tid>>5;
    if(blk < PB_W3){
        int w = blk/64, rem = blk%64;
        const float* W = (w==0)?Wq:(w==1)?Wk:Wv;
        __half*     T  = (w==0)?wq:(w==1)?wk:wv;
        wtile_body(W, T, DV, DV, (rem%8)*32, (rem/8)*32, tx, ty, sm);
    } else if(blk < PB_W1){
        int rem = blk - PB_W3;
        wtile_body(W1, w1, DV, DFF, (rem%8)*32, (rem/8)*32, tx, ty, sm);
    } else if(blk < PB_W2){
        int rem = blk - PB_W1;
        wtile_body(W2, w2, DFF, DV, (rem%16)*32, (rem/16)*32, tx, ty, sm);
    } else if(blk < PB_Y){
        int gid = (blk - PB_W2)*256 + tid;
        yprep_body(y, yr, gid);
    } else {
        int row = (blk - PB_Y)*8 + ty;
        ln_body(x, xn, ln0_g, ln0_b, row, tx);
    }
}

__global__ __launch_bounds__(256)
void ln_kernel(const float* __restrict__ src, __half* __restrict__ dst,
               const float* __restrict__ gamma, const float* __restrict__ beta)
{
    ln_body(src, dst, gamma, beta, blockIdx.x*8 + (threadIdx.x>>5), threadIdx.x&31);
}

// ---------------- GEMM mainloop (3-stage cp.async, BK=32) ----------------
#define ASTG (256*48)
#define BSTG (64*48)
#define SMEM_GEMM ((3*ASTG + 3*BSTG)*2)
#define ESTR 72   // fp32 staging stride (72 mod 32 = 8)

template<int KDIM>
__device__ __forceinline__ void gemm_main(const __half* __restrict__ A,
                                          const __half* __restrict__ Wt,
                                          __half* dyn, float acc[2][8][4],
                                          int rowBase, int colBase, int tid)
{
    __half* As = dyn;
    __half* Bs = dyn + 3*ASTG;
    const int warp = tid>>5, lane = tid&31, g = lane>>2, c = lane&3;
    const int NK = KDIM/32;
    const int ar = tid>>2, ap = tid&3;
    const int br = tid>>2, bp = tid&3;

    #pragma unroll
    for(int st=0; st<2; st++){
        #pragma unroll
        for(int i=0;i<4;i++){
            int row = ar + i*64;
            cpa16(&As[st*ASTG + row*48 + ap*8], A + (rowBase+row)*KDIM + st*32 + ap*8);
        }
        cpa16(&Bs[st*BSTG + br*48 + bp*8], Wt + (colBase+br)*KDIM + st*32 + bp*8);
        asm volatile("cp.async.commit_group;");
    }

    #pragma unroll 1
    for(int kt=0; kt<NK; kt++){
        const int cur = kt%3;
        asm volatile("cp.async.wait_group 1;");
        __syncthreads();
        if(kt+2 < NK){
            const int nx = (kt+2)%3;
            #pragma unroll
            for(int i=0;i<4;i++){
                int row = ar + i*64;
                cpa16(&As[nx*ASTG + row*48 + ap*8],
                      A + (rowBase+row)*KDIM + (kt+2)*32 + ap*8);
            }
            cpa16(&Bs[nx*BSTG + br*48 + bp*8],
                  Wt + (colBase+br)*KDIM + (kt+2)*32 + bp*8);
        }
        asm volatile("cp.async.commit_group;");

        #pragma unroll
        for(int ks=0;ks<2;ks++){
            unsigned af[2][4];
            #pragma unroll
            for(int mt=0;mt<2;mt++){
                int r = warp*32 + mt*16 + g;
                uint2 lo = *(const uint2*)&As[cur*ASTG +  r   *48 + ks*16 + 4*c];
                uint2 hi = *(const uint2*)&As[cur*ASTG + (r+8)*48 + ks*16 + 4*c];
                af[mt][0]=lo.x; af[mt][1]=hi.x; af[mt][2]=lo.y; af[mt][3]=hi.y;
            }
            #pragma unroll
            for(int nt=0;nt<8;nt++){
                uint2 bb = *(const uint2*)&Bs[cur*BSTG + (nt*8+g)*48 + ks*16 + 4*c];
                mmah(acc[0][nt], af[0][0],af[0][1],af[0][2],af[0][3], bb.x,bb.y);
                mmah(acc[1][nt], af[1][0],af[1][1],af[1][2],af[1][3], bb.x,bb.y);
            }
        }
    }
    __syncthreads();   // all warps done reading stages before E reuse
}

// stage acc(+bias)(+gelu) into fp32 E[256][ESTR]
__device__ __forceinline__ void epi_stage(float* E, float acc[2][8][4],
                                          const float* __restrict__ bias,
                                          int colBase, int do_gelu, int tid)
{
    const int warp = tid>>5, lane = tid&31, g = lane>>2, c = lane&3;
    #pragma unroll
    for(int mt=0;mt<2;mt++)
    #pragma unroll
    for(int i=0;i<2;i++){
        int r = warp*32 + mt*16 + g + i*8;
        #pragma unroll
        for(int nt=0;nt<8;nt++){
            int col0 = nt*8 + 2*c;
            float v0 = acc[mt][nt][i*2+0] + bias[colBase+col0];
            float v1 = acc[mt][nt][i*2+1] + bias[colBase+col0+1];
            if(do_gelu){ v0 = gelu1(v0); v1 = gelu1(v1); }
            float2 o; o.x=v0; o.y=v1;
            *(float2*)&E[r*ESTR + col0] = o;
        }
    }
}

// ---------------- fused QKV GEMM (z: 0=Q, 1=K, 2=V) ----------------
__global__ __launch_bounds__(256,2)
void gemm_qkv(const __half* __restrict__ xn, const __half* __restrict__ yr,
              const __half* __restrict__ wq, const __half* __restrict__ wk,
              const __half* __restrict__ wv,
              const float* __restrict__ bq, const float* __restrict__ bk,
              const float* __restrict__ bv,
              float* __restrict__ Qout, __half* __restrict__ Kout,
              __half* __restrict__ Vout)
{
    extern __shared__ __half dyn[];
    const int tid = threadIdx.x;
    const int z = blockIdx.z;
    const int rowBase = blockIdx.y*256;
    const int colBase = blockIdx.x*64;
    const __half* A  = (z==0) ? xn : yr;
    const __half* Wt = (z==0) ? wq : (z==1) ? wk : wv;
    const float* bias = (z==0) ? bq : (z==1) ? bk : bv;

    float acc[2][8][4];
    #pragma unroll
    for(int mt=0;mt<2;mt++)
        #pragma unroll
        for(int nt=0;nt<8;nt++)
            #pragma unroll
            for(int j=0;j<4;j++) acc[mt][nt][j]=0.f;

    gemm_main<256>(A, Wt, dyn, acc, rowBase, colBase, tid);
    float* E = (float*)dyn;
    epi_stage(E, acc, bias, colBase, 0, tid);
    __syncthreads();

    const int bb_ = rowBase>>11, n0 = rowBase&2047;
    const int h0 = colBase>>5;
    if(z==0){
        #pragma unroll
        for(int head=0;head<2;head++){
            float* base = Qout + ((size_t)(bb_*HH + h0+head)*NN + n0)*32;
            #pragma unroll
            for(int it=0;it<8;it++){
                int idx = it*256 + tid;
                int row = idx>>3, j = idx&7;
                float4 v = *(const float4*)&E[row*ESTR + head*32 + 4*j];
                ((float4*)base)[row*8 + j] = v;
            }
        }
    } else if(z==1){
        #pragma unroll
        for(int head=0;head<2;head++){
            __half* base = Kout + ((size_t)(bb_*HH + h0+head)*NN + n0)*32;
            #pragma unroll
            for(int it=0;it<4;it++){
                int idx = it*256 + tid;
                int row = idx>>2, q = idx&3;
                float v[8];
                #pragma unroll
                for(int j=0;j<8;j++){
                    int pd = 8*q + j;
                    int dl = (pd&~15) | iquad16(pd&15);
                    v[j] = E[row*ESTR + head*32 + dl];
                }
                uint4 u; u.x=h2u(v[0],v[1]); u.y=h2u(v[2],v[3]);
                        u.z=h2u(v[4],v[5]); u.w=h2u(v[6],v[7]);
                ((uint4*)(base + row*32))[q] = u;
            }
        }
    } else {
        #pragma unroll
        for(int it=0;it<8;it++){
            int idx = it*256 + tid;
            int colIdx = idx&63, q = idx>>6;   // q 0..31
            int h = h0 + (colIdx>>5), d = colIdx&31;
            __half* base = Vout + ((size_t)(bb_*HH + h)*32 + d)*NN + n0;
            float v[8];
            #pragma unroll
            for(int j=0;j<8;j++){
                int pt = 8*q + j;
                int tl = (pt&~15) | iquad16(pt&15);
                v[j] = E[tl*ESTR + colIdx];
            }
            uint4 u; u.x=h2u(v[0],v[1]); u.y=h2u(v[2],v[3]);
                    u.z=h2u(v[4],v[5]); u.w=h2u(v[6],v[7]);
            ((uint4*)base)[q] = u;
        }
    }
}

// ---------------- FFN1: gelu -> H1 fp16 quad16 ----------------
__global__ __launch_bounds__(256,2)
void gemm_ffn1(const __half* __restrict__ On, const __half* __restrict__ w1,
               const float* __restrict__ b1, __half* __restrict__ H1)
{
    extern __shared__ __half dyn[];
    const int tid = threadIdx.x;
    const int rowBase = blockIdx.y*256;
    const int colBase = blockIdx.x*64;

    float acc[2][8][4];
    #pragma unroll
    for(int mt=0;mt<2;mt++)
        #pragma unroll
        for(int nt=0;nt<8;nt++)
            #pragma unroll
            for(int j=0;j<4;j++) acc[mt][nt][j]=0.f;

    gemm_main<256>(On, w1, dyn, acc, rowBase, colBase, tid);
    float* E = (float*)dyn;
    epi_stage(E, acc, b1, colBase, 1, tid);
    __syncthreads();

    #pragma unroll
    for(int it=0;it<8;it++){
        int idx = it*256 + tid;
        int row = idx>>3, p = idx&7;
        float v[8];
        #pragma unroll
        for(int j=0;j<8;j++){
            int lp = 8*p + j;
            int lc = (lp&~15) | iquad16(lp&15);
            v[j] = E[row*ESTR + lc];
        }
        uint4 u; u.x=h2u(v[0],v[1]); u.y=h2u(v[2],v[3]);
                u.z=h2u(v[4],v[5]); u.w=h2u(v[6],v[7]);
        ((uint4*)(H1 + (size_t)(rowBase+row)*DFF + colBase))[p] = u;
    }
}

// ---------------- FFN2: resid + acc + bias -> fp32 out ----------------
__global__ __launch_bounds__(256,2)
void gemm_ffn2(const __half* __restrict__ H1, const __half* __restrict__ w2,
               const float* __restrict__ b2, float* __restrict__ out,
               const float* __restrict__ resid)
{
    extern __shared__ __half dyn[];
    const int tid = threadIdx.x;
    const int rowBase = blockIdx.y*256;
    const int colBase = blockIdx.x*64;

    float acc[2][8][4];
    #pragma unroll
    for(int mt=0;mt<2;mt++)
        #pragma unroll
        for(int nt=0;nt<8;nt++)
            #pragma unroll
            for(int j=0;j<4;j++) acc[mt][nt][j]=0.f;

    gemm_main<512>(H1, w2, dyn, acc, rowBase, colBase, tid);
    float* E = (float*)dyn;
    epi_stage(E, acc, b2, colBase, 0, tid);
    __syncthreads();

    #pragma unroll
    for(int it=0;it<16;it++){
        int idx = it*256 + tid;
        int row = idx>>4, j = idx&15;
        float4 v  = *(const float4*)&E[row*ESTR + 4*j];
        const float4 rr = *(const float4*)&resid[(size_t)(rowBase+row)*256 + colBase + 4*j];
        v.x += rr.x; v.y += rr.y; v.z += rr.z; v.w += rr.w;
        *(float4*)&out[(size_t)(rowBase+row)*256 + colBase + 4*j] = v;
    }
}

// ---------------- fp16 tensor-core flash attention + per-head Q residual ----------------
__global__ __launch_bounds__(256,2)
void attn_tc(const float* __restrict__ Q, const __half* __restrict__ K,
             const __half* __restrict__ V, float* __restrict__ O)
{
    __shared__ __align__(16) __half Ks[2][64*48];
    __shared__ __align__(16) __half Vs[2][32*80];
    const int tid  = threadIdx.x;
    const int warp = tid>>5, lane = tid&31, g = lane>>2, c = lane&3;
    const int bh = blockIdx.y;
    const int b  = bh>>3, h = bh&7;
    const int qbase = blockIdx.x*128;
    const float*  Qg = Q + (bh*NN + qbase)*32;
    const __half* Kg = K + (long)bh*NN*32;
    const __half* Vg = V + (long)bh*32*NN;

    const float QS = 0.0625f * 1.44269504088896341f;
    unsigned qf[2][4];
    {
        int r0 = warp*16 + g;
        #pragma unroll
        for(int kh=0;kh<2;kh++){
            int d0 = kh*16 + 2*c;
            qf[kh][0] = h2u(Qg[ r0   *32 + d0  ]*QS, Qg[ r0   *32 + d0+1]*QS);
            qf[kh][1] = h2u(Qg[(r0+8)*32 + d0  ]*QS, Qg[(r0+8)*32 + d0+1]*QS);
            qf[kh][2] = h2u(Qg[ r0   *32 + d0+8]*QS, Qg[ r0   *32 + d0+9]*QS);
            qf[kh][3] = h2u(Qg[(r0+8)*32 + d0+8]*QS, Qg[(r0+8)*32 + d0+9]*QS);
        }
    }

    float oacc[4][4];
    #pragma unroll
    for(int nt=0;nt<4;nt++)
        #pragma unroll
        for(int j=0;j<4;j++) oacc[nt][j]=0.f;
    float lacc[4] = {0.f,0.f,0.f,0.f};
    const unsigned ones = (g==0) ? 0x3C003C00u : 0u;

    cpa16(&Ks[0][(tid>>2)*48 + (tid&3)*8], Kg + (tid>>2)*32 + (tid&3)*8);
    cpa16(&Vs[0][(tid>>3)*80 + (tid&7)*8], Vg + (tid>>3)*NN + (tid&7)*8);
    asm volatile("cp.async.commit_group;");

    #pragma unroll 1
    for(int kt=0; kt<NN/64; kt++){
        int buf = kt&1;
        __syncthreads();
        if(kt+1 < NN/64){
            cpa16(&Ks[buf^1][(tid>>2)*48 + (tid&3)*8],
                  Kg + ((kt+1)*64 + (tid>>2))*32 + (tid&3)*8);
            cpa16(&Vs[buf^1][(tid>>3)*80 + (tid&7)*8],
                  Vg + (tid>>3)*NN + (kt+1)*64 + (tid&7)*8);
            asm volatile("cp.async.commit_group;");
            asm volatile("cp.async.wait_group 1;");
        } else {
            asm volatile("cp.async.wait_group 0;");
        }
        __syncthreads();

        float sv[8][4];
        #pragma unroll
        for(int nt=0;nt<8;nt++)
            #pragma unroll
            for(int j=0;j<4;j++) sv[nt][j]=0.f;
        #pragma unroll
        for(int kh=0;kh<2;kh++){
            #pragma unroll
            for(int nt=0;nt<8;nt++){
                uint2 bb = *(const uint2*)&Ks[buf][(nt*8+g)*48 + kh*16 + 4*c];
                mmah(sv[nt], qf[kh][0],qf[kh][1],qf[kh][2],qf[kh][3], bb.x,bb.y);
            }
        }
        unsigned ph[8][2];
        #pragma unroll
        for(int nt=0;nt<8;nt++){
            ph[nt][0] = ex2h2(h2u(sv[nt][0], sv[nt][1]));
            ph[nt][1] = ex2h2(h2u(sv[nt][2], sv[nt][3]));
        }
        #pragma unroll
        for(int ks=0;ks<4;ks++){
            unsigned a0 = ph[2*ks][0], a1 = ph[2*ks][1];
            unsigned a2 = ph[2*ks+1][0], a3 = ph[2*ks+1][1];
            #pragma unroll
            for(int nt=0;nt<4;nt++){
                uint2 bb = *(const uint2*)&Vs[buf][(nt*8+g)*80 + ks*16 + 4*c];
                mmah(oacc[nt], a0,a1,a2,a3, bb.x,bb.y);
            }
            mmah(lacc, a0,a1,a2,a3, ones, ones);
        }
    }

    float l0 = __shfl_sync(0xffffffffu, lacc[0], lane & ~3);
    float l1 = __shfl_sync(0xffffffffu, lacc[2], lane & ~3);
    float inv0 = 1.f/l0, inv1 = 1.f/l1;

    #pragma unroll
    for(int i=0;i<2;i++){
        int rloc = warp*16 + g + i*8;
        int row  = qbase + rloc;
        float inv = (i==0) ? inv0 : inv1;
        #pragma unroll
        for(int nt=0;nt<4;nt++){
            int col = nt*8 + 2*c;
            float q0 = Qg[rloc*32 + col];
            float q1 = Qg[rloc*32 + col + 1];
            float2 o;
            o.x = q0 + oacc[nt][i*2+0]*inv;
            o.y = q1 + oacc[nt][i*2+1]*inv;
            *(float2*)&O[((long)b*NN + row)*DV + h*32 + col] = o;
        }
    }
}

// ---------------- launch ----------------
extern "C" void kernel_launch(void* const* d_in, const int* /*in_sizes*/, int /*n_in*/,
                              void* d_out, int /*out_size*/)
{
    const float* x     = (const float*)d_in[0];
    const float* y     = (const float*)d_in[1];
    const float* Wq    = (const float*)d_in[2];
    const float* bq    = (const float*)d_in[3];
    const float* Wk    = (const float*)d_in[4];
    const float* bk    = (const float*)d_in[5];
    const float* Wv    = (const float*)d_in[6];
    const float* bv    = (const float*)d_in[7];
    const float* W1    = (const float*)d_in[8];
    const float* b1    = (const float*)d_in[9];
    const float* W2    = (const float*)d_in[10];
    const float* b2    = (const float*)d_in[11];
    const float* ln0_g = (const float*)d_in[12];
    const float* ln0_b = (const float*)d_in[13];
    const float* ln1_g = (const float*)d_in[14];
    const float* ln1_b = (const float*)d_in[15];
    float* out = (float*)d_out;

    float *Q,*O;
    __half *xn,*yr,*K,*V,*On,*H1,*wq,*wk,*wv,*w1,*w2;
    cudaGetSymbolAddress((void**)&xn, g_xn);
    cudaGetSymbolAddress((void**)&yr, g_yr);
    cudaGetSymbolAddress((void**)&Q,  g_Q);
    cudaGetSymbolAddress((void**)&K,  g_K);
    cudaGetSymbolAddress((void**)&V,  g_V);
    cudaGetSymbolAddress((void**)&O,  g_O);
    cudaGetSymbolAddress((void**)&On, g_On);
    cudaGetSymbolAddress((void**)&H1, g_H1);
    cudaGetSymbolAddress((void**)&wq, g_Wq);
    cudaGetSymbolAddress((void**)&wk, g_Wk);
    cudaGetSymbolAddress((void**)&wv, g_Wv);
    cudaGetSymbolAddress((void**)&w1, g_W1);
    cudaGetSymbolAddress((void**)&w2, g_W2);

    cudaFuncSetAttribute(gemm_qkv,  cudaFuncAttributeMaxDynamicSharedMemorySize, SMEM_GEMM);
    cudaFuncSetAttribute(gemm_ffn1, cudaFuncAttributeMaxDynamicSharedMemorySize, SMEM_GEMM);
    cudaFuncSetAttribute(gemm_ffn2, cudaFuncAttributeMaxDynamicSharedMemorySize, SMEM_GEMM);

    prep_all<<<PB_LN, 256>>>(Wq, Wk, Wv, W1, W2, y, x, ln0_g, ln0_b,
                             wq, wk, wv, w1, w2, yr, xn);
    gemm_qkv<<<dim3(4, 64, 3), 256, SMEM_GEMM>>>(xn, yr, wq, wk, wv,
                                                 bq, bk, bv, Q, K, V);
    attn_tc<<<dim3(NN/128, BB*HH), 256>>>(Q, K, V, O);
    ln_kernel<<<MROWS/8, 256>>>(O, On, ln1_g, ln1_b);
    gemm_ffn1<<<dim3(8, 64), 256, SMEM_GEMM>>>(On, w1, b1, H1);
    gemm_ffn2<<<dim3(4, 64), 256, SMEM_GEMM>>>(H1, w2, b2, out, O);
}